// round 5
// baseline (speedup 1.0000x reference)
#include <cuda_runtime.h>

#define NN 512
#define RR 16
#define HH 16
#define TI 4               // i-rows per warp
#define JS 32              // j slices (partial buffers)
#define JPW (NN/JS)        // 16 j per warp
#define WPB 8              // warps per block
#define BLK 256
#define NIG (NN/TI)        // 128 i-groups
#define GRID_AC ((NIG/WPB)*JS)   // 16*32 = 512 blocks

// smearing constants (f32)
#define SM_START 0.006737946999085467f
#define SM_MSTEP ((1.0f - SM_START) * (1.0f/15.0f))
#define SM_SBETA (0.125f * (1.0f - SM_START))
#define SM_BETA  (1.0f / (SM_SBETA * SM_SBETA))
#define PI_OVER5 0.6283185307179586f

// scratch
__device__ __align__(16) float g_sm[NN*NN*RR];   // [i][j][r]  16MB
__device__ float4 g_diffn4[NN*NN];               // [i][j] -> (d0,d1,d2,0)
__device__ float g_bkp [JS*NN*48];
__device__ float g_bqp [JS*NN*48];
__device__ float g_Sp  [JS*NN*48];
__device__ float g_S   [NN*48];
__device__ float g_lr  [NN*1024];                // left(512)|right(512)
__device__ float g_bk2p[JS*NN*48];
__device__ float g_bq2p[JS*NN*48];

// ---------------------------------------------------------------------------
// Phase G: pair-parallel geometry + smearing. One thread per (i,j).
// ---------------------------------------------------------------------------
__global__ __launch_bounds__(256) void phaseG(const float* __restrict__ x)
{
    const int i = blockIdx.x >> 1;
    const int j = ((blockIdx.x & 1) << 8) + threadIdx.x;

    const float xi0 = __ldg(&x[i*3+0]);
    const float xi1 = __ldg(&x[i*3+1]);
    const float xi2 = __ldg(&x[i*3+2]);
    const float dx = xi0 - __ldg(&x[j*3+0]);
    const float dy = xi1 - __ldg(&x[j*3+1]);
    const float dz = xi2 - __ldg(&x[j*3+2]);

    const float nsq = fmaf(dx,dx, fmaf(dy,dy, fmaf(dz,dz, 1e-6f)));
    const float rin = rsqrtf(nsq);
    const float d   = nsq * rin;
    const float inv = rin * rin;

    g_diffn4[i*NN + j] = make_float4(dx*inv, dy*inv, dz*inv, 0.f);

    const float e   = __expf(-d);
    const float cut = (d < 5.0f) ? 0.5f*(__cosf(d*PI_OVER5) + 1.0f) : 0.0f;

    float4* gp = (float4*)&g_sm[(i*NN + j)*16];
    #pragma unroll
    for (int rg = 0; rg < 4; rg++) {
        float4 v;
        float u0 = e - (SM_START + SM_MSTEP*(float)(rg*4+0));
        float u1 = e - (SM_START + SM_MSTEP*(float)(rg*4+1));
        float u2 = e - (SM_START + SM_MSTEP*(float)(rg*4+2));
        float u3 = e - (SM_START + SM_MSTEP*(float)(rg*4+3));
        v.x = cut * __expf(-SM_BETA*u0*u0);
        v.y = cut * __expf(-SM_BETA*u1*u1);
        v.z = cut * __expf(-SM_BETA*u2*u2);
        v.w = cut * __expf(-SM_BETA*u3*u3);
        gp[rg] = v;
    }
}

// ---------------------------------------------------------------------------
// Phase A: first contraction. Block = (ig-block of 8 warps, j-slice of 16).
// K|Q weight slice staged in smem (padded: Q at +4112 floats -> bank shift 16).
// Warp: 4 i's; lanes 0-15 K path (c=lane), 16-31 Q path. sm/df via gather.
// ---------------------------------------------------------------------------
__global__ __launch_bounds__(BLK, 3) void phaseA(const float* __restrict__ W)
{
    __shared__ __align__(16) float s_W[4112 + 4096];       // K[4096] pad16 Q[4096]
    __shared__ __align__(16) float4 s_smT[WPB][TI][4];
    __shared__ __align__(16) float4 s_df[WPB][TI];

    const int tid  = threadIdx.x;
    const int w    = tid >> 5;
    const int lane = tid & 31;
    const int igb  = blockIdx.x >> 5;        // / JS
    const int js   = blockIdx.x & (JS-1);
    const int i0   = (igb*WPB + w)*TI;
    const int c    = lane & 15;
    const bool isQ = lane >= 16;
    const int j0   = js*JPW;

    {   // stage K[j0:j0+16] and Q[j0:j0+16] (4096 floats each)
        float4* dst = (float4*)s_W;
        const float4* srcK = (const float4*)(W + j0*(RR*HH));
        const float4* srcQ = (const float4*)(W + NN*RR*HH + j0*(RR*HH));
        #pragma unroll
        for (int f = 0; f < 4; f++) dst[tid + f*BLK]        = srcK[tid + f*BLK];
        #pragma unroll
        for (int f = 0; f < 4; f++) dst[1028 + tid + f*BLK] = srcQ[tid + f*BLK];
    }

    float accP[TI][3], accS[TI][3];
    #pragma unroll
    for (int t = 0; t < TI; t++)
        #pragma unroll
        for (int b = 0; b < 3; b++) { accP[t][b] = 0.f; accS[t][b] = 0.f; }

    __syncthreads();

    #pragma unroll 2
    for (int jl = 0; jl < JPW; jl++) {
        const int j = j0 + jl;
        if (lane < 16) {
            int t = lane >> 2, rg = lane & 3;
            s_smT[w][t][rg] = *(const float4*)&g_sm[((i0+t)*NN + j)*16 + rg*4];
        } else if (lane < 20) {
            s_df[w][lane-16] = g_diffn4[(i0 + lane-16)*NN + j];
        }
        __syncwarp();

        const float* wp = &s_W[(isQ ? 4112 : 0) + jl*256 + c];
        float P0=0.f, P1=0.f, P2=0.f, P3=0.f;
        #pragma unroll
        for (int rg = 0; rg < 4; rg++) {
            float w0 = wp[(rg*4+0)*16];
            float w1 = wp[(rg*4+1)*16];
            float w2 = wp[(rg*4+2)*16];
            float w3 = wp[(rg*4+3)*16];
            float4 a0 = s_smT[w][0][rg];
            float4 a1 = s_smT[w][1][rg];
            float4 a2 = s_smT[w][2][rg];
            float4 a3 = s_smT[w][3][rg];
            P0 = fmaf(a0.x,w0, fmaf(a0.y,w1, fmaf(a0.z,w2, fmaf(a0.w,w3, P0))));
            P1 = fmaf(a1.x,w0, fmaf(a1.y,w1, fmaf(a1.z,w2, fmaf(a1.w,w3, P1))));
            P2 = fmaf(a2.x,w0, fmaf(a2.y,w1, fmaf(a2.z,w2, fmaf(a2.w,w3, P2))));
            P3 = fmaf(a3.x,w0, fmaf(a3.y,w1, fmaf(a3.z,w2, fmaf(a3.w,w3, P3))));
        }

        float4 df0 = s_df[w][0], df1 = s_df[w][1];
        float4 df2 = s_df[w][2], df3 = s_df[w][3];
        accP[0][0] = fmaf(P0, df0.x, accP[0][0]);
        accP[0][1] = fmaf(P0, df0.y, accP[0][1]);
        accP[0][2] = fmaf(P0, df0.z, accP[0][2]);
        accP[1][0] = fmaf(P1, df1.x, accP[1][0]);
        accP[1][1] = fmaf(P1, df1.y, accP[1][1]);
        accP[1][2] = fmaf(P1, df1.z, accP[1][2]);
        accP[2][0] = fmaf(P2, df2.x, accP[2][0]);
        accP[2][1] = fmaf(P2, df2.y, accP[2][1]);
        accP[2][2] = fmaf(P2, df2.z, accP[2][2]);
        accP[3][0] = fmaf(P3, df3.x, accP[3][0]);
        accP[3][1] = fmaf(P3, df3.y, accP[3][1]);
        accP[3][2] = fmaf(P3, df3.z, accP[3][2]);

        if (!isQ) {   // accS: lane c plays r=c.  sm[t][c] scalar from s_smT row t
            #pragma unroll
            for (int t = 0; t < TI; t++) {
                float sv = ((const float*)&s_smT[w][t][0])[c];
                float4 df = s_df[w][t];
                accS[t][0] = fmaf(sv, df.x, accS[t][0]);
                accS[t][1] = fmaf(sv, df.y, accS[t][1]);
                accS[t][2] = fmaf(sv, df.z, accS[t][2]);
            }
        }
        __syncwarp();
    }

    float* outp = isQ ? g_bqp : g_bkp;
    #pragma unroll
    for (int t = 0; t < TI; t++)
        #pragma unroll
        for (int b = 0; b < 3; b++)
            outp[(js*NN + (i0+t))*48 + c*3 + b] = accP[t][b];
    if (!isQ) {
        #pragma unroll
        for (int t = 0; t < TI; t++)
            #pragma unroll
            for (int b = 0; b < 3; b++)
                g_Sp[(js*NN + (i0+t))*48 + c*3 + b] = accS[t][b];  // c == r
    }
}

// ---------------------------------------------------------------------------
// Phase B: coalesced merge of partials, att outer, MLP1 -> g_lr; merge S.
// ---------------------------------------------------------------------------
__global__ __launch_bounds__(256) void phaseB(const float* __restrict__ W1,
                                              const float* __restrict__ b1,
                                              const float* __restrict__ W2)
{
    const int i = blockIdx.x;
    const int tid = threadIdx.x;
    __shared__ __align__(16) float s_m[3][JS][64];   // bkp | bqp | Sp rows
    __shared__ float s_bk[48], s_bq[48], s_att[256], s_y[16];

    // load 3*JS*12 float4 = 1152 coalesced
    #pragma unroll
    for (int k = 0; k < 5; k++) {
        int idx = tid + k*256;
        if (idx < 3*JS*12) {
            int v = idx / (JS*12), rem = idx % (JS*12);
            int js = rem / 12, f = rem % 12;
            const float4* src = (v == 0) ? (const float4*)g_bkp
                              : (v == 1) ? (const float4*)g_bqp
                                         : (const float4*)g_Sp;
            *(float4*)&s_m[v][js][f*4] = src[(js*NN + i)*12 + f];
        }
    }
    __syncthreads();

    if (tid < 144) {
        int v = tid / 48, e = tid % 48;
        float s = 0.f;
        #pragma unroll
        for (int js = 0; js < JS; js++) s += s_m[v][js][e];
        if (v == 0) s_bk[e] = s;
        else if (v == 1) s_bq[e] = s;
        else g_S[i*48 + e] = s;
    }
    __syncthreads();

    {
        int h = tid >> 4, g = tid & 15;
        s_att[tid] = s_bk[h*3+0]*s_bq[g*3+0] + s_bk[h*3+1]*s_bq[g*3+1]
                   + s_bk[h*3+2]*s_bq[g*3+2];
    }
    __syncthreads();

    {
        int h = tid >> 4, t = tid & 15;
        const float* w = W1 + h*256 + t;
        float p = 0.f;
        #pragma unroll
        for (int q = 0; q < 16; q++) p = fmaf(s_att[t + 16*q], w[16*q], p);
        #pragma unroll
        for (int m = 8; m >= 1; m >>= 1) p += __shfl_xor_sync(0xffffffffu, p, m, 16);
        if (t == 0) {
            float y = p + b1[h];
            s_y[h] = y / (1.0f + __expf(-y));
        }
    }
    __syncthreads();

    #pragma unroll
    for (int q = 0; q < 4; q++) {
        int m = tid + 256*q;
        const float* w = W2 + m*16;
        float a = 0.f;
        #pragma unroll
        for (int o = 0; o < 16; o++) a = fmaf(s_y[o], w[o], a);
        g_lr[i*1024 + m] = a;
    }
}

// ---------------------------------------------------------------------------
// Phase C: second contraction, right-stream. lr-right slice staged in smem
// (row 544 floats: K at +0, Q at +272 -> bank shift 16).
// ---------------------------------------------------------------------------
__global__ __launch_bounds__(BLK, 3) void phaseC()
{
    __shared__ __align__(16) float s_R[JPW*544];
    __shared__ __align__(16) float4 s_smT[WPB][TI][4];
    __shared__ __align__(16) float4 s_df[WPB][TI];

    const int tid  = threadIdx.x;
    const int w    = tid >> 5;
    const int lane = tid & 31;
    const int igb  = blockIdx.x >> 5;
    const int js   = blockIdx.x & (JS-1);
    const int i0   = (igb*WPB + w)*TI;
    const int c    = lane & 15;
    const bool isQ = lane >= 16;
    const int j0   = js*JPW;

    {   // stage right half of lr for 16 j's (128 float4 per j)
        float4* dst = (float4*)s_R;
        const float4* src = (const float4*)g_lr;
        #pragma unroll
        for (int f = 0; f < 8; f++) {
            int idx = tid + f*BLK;              // 0..2047
            int jl = idx >> 7, o = idx & 127;
            dst[jl*136 + o + ((o >= 64) ? 4 : 0)] = src[(j0+jl)*256 + 128 + o];
        }
    }

    float accP[TI][3];
    #pragma unroll
    for (int t = 0; t < TI; t++)
        #pragma unroll
        for (int b = 0; b < 3; b++) accP[t][b] = 0.f;

    __syncthreads();

    #pragma unroll 2
    for (int jl = 0; jl < JPW; jl++) {
        const int j = j0 + jl;
        if (lane < 16) {
            int t = lane >> 2, rg = lane & 3;
            s_smT[w][t][rg] = *(const float4*)&g_sm[((i0+t)*NN + j)*16 + rg*4];
        } else if (lane < 20) {
            s_df[w][lane-16] = g_diffn4[(i0 + lane-16)*NN + j];
        }
        __syncwarp();

        const float* wp = &s_R[jl*544 + (isQ ? 272 : 0) + c];
        float P0=0.f, P1=0.f, P2=0.f, P3=0.f;
        #pragma unroll
        for (int rg = 0; rg < 4; rg++) {
            float w0 = wp[(rg*4+0)*16];
            float w1 = wp[(rg*4+1)*16];
            float w2 = wp[(rg*4+2)*16];
            float w3 = wp[(rg*4+3)*16];
            float4 a0 = s_smT[w][0][rg];
            float4 a1 = s_smT[w][1][rg];
            float4 a2 = s_smT[w][2][rg];
            float4 a3 = s_smT[w][3][rg];
            P0 = fmaf(a0.x,w0, fmaf(a0.y,w1, fmaf(a0.z,w2, fmaf(a0.w,w3, P0))));
            P1 = fmaf(a1.x,w0, fmaf(a1.y,w1, fmaf(a1.z,w2, fmaf(a1.w,w3, P1))));
            P2 = fmaf(a2.x,w0, fmaf(a2.y,w1, fmaf(a2.z,w2, fmaf(a2.w,w3, P2))));
            P3 = fmaf(a3.x,w0, fmaf(a3.y,w1, fmaf(a3.z,w2, fmaf(a3.w,w3, P3))));
        }

        float4 df0 = s_df[w][0], df1 = s_df[w][1];
        float4 df2 = s_df[w][2], df3 = s_df[w][3];
        accP[0][0] = fmaf(P0, df0.x, accP[0][0]);
        accP[0][1] = fmaf(P0, df0.y, accP[0][1]);
        accP[0][2] = fmaf(P0, df0.z, accP[0][2]);
        accP[1][0] = fmaf(P1, df1.x, accP[1][0]);
        accP[1][1] = fmaf(P1, df1.y, accP[1][1]);
        accP[1][2] = fmaf(P1, df1.z, accP[1][2]);
        accP[2][0] = fmaf(P2, df2.x, accP[2][0]);
        accP[2][1] = fmaf(P2, df2.y, accP[2][1]);
        accP[2][2] = fmaf(P2, df2.z, accP[2][2]);
        accP[3][0] = fmaf(P3, df3.x, accP[3][0]);
        accP[3][1] = fmaf(P3, df3.y, accP[3][1]);
        accP[3][2] = fmaf(P3, df3.z, accP[3][2]);
        __syncwarp();
    }

    float* outp = isQ ? g_bq2p : g_bk2p;
    #pragma unroll
    for (int t = 0; t < TI; t++)
        #pragma unroll
        for (int b = 0; b < 3; b++)
            outp[(js*NN + (i0+t))*48 + c*3 + b] = accP[t][b];
}

// ---------------------------------------------------------------------------
// Phase D: coalesced merge + left⊗S term, att outer, MLP2, output.
// ---------------------------------------------------------------------------
__global__ __launch_bounds__(256) void phaseD(const float* __restrict__ W3,
                                              const float* __restrict__ b3,
                                              const float* __restrict__ W4,
                                              const float* __restrict__ b4,
                                              float* __restrict__ out)
{
    const int i = blockIdx.x;
    const int tid = threadIdx.x;
    __shared__ __align__(16) float s_m[2][JS][64];
    __shared__ float s_bk[48], s_bq[48], s_att[256], s_y[16];

    #pragma unroll
    for (int k = 0; k < 3; k++) {
        int idx = tid + k*256;
        if (idx < 2*JS*12) {
            int v = idx / (JS*12), rem = idx % (JS*12);
            int js = rem / 12, f = rem % 12;
            const float4* src = (v == 0) ? (const float4*)g_bk2p
                                         : (const float4*)g_bq2p;
            *(float4*)&s_m[v][js][f*4] = src[(js*NN + i)*12 + f];
        }
    }
    __syncthreads();

    if (tid < 96) {
        int v = tid / 48, e = tid % 48;
        int cc = e / 3, b = e % 3;
        float s = 0.f;
        #pragma unroll
        for (int js = 0; js < JS; js++) s += s_m[v][js][e];
        const float* lp = g_lr + i*1024 + (v ? 256 : 0) + cc;
        const float* sp = g_S  + i*48 + b;
        #pragma unroll
        for (int r = 0; r < 16; r++) s = fmaf(lp[r*16], sp[r*3], s);
        if (v == 0) s_bk[e] = s; else s_bq[e] = s;
    }
    __syncthreads();

    {
        int h = tid >> 4, g = tid & 15;
        s_att[tid] = s_bk[h*3+0]*s_bq[g*3+0] + s_bk[h*3+1]*s_bq[g*3+1]
                   + s_bk[h*3+2]*s_bq[g*3+2];
    }
    __syncthreads();

    {
        int h = tid >> 4, t = tid & 15;
        const float* w = W3 + h*256 + t;
        float p = 0.f;
        #pragma unroll
        for (int q = 0; q < 16; q++) p = fmaf(s_att[t + 16*q], w[16*q], p);
        #pragma unroll
        for (int m = 8; m >= 1; m >>= 1) p += __shfl_xor_sync(0xffffffffu, p, m, 16);
        if (t == 0) {
            float y = p + b3[h];
            s_y[h] = y / (1.0f + __expf(-y));
        }
    }
    __syncthreads();

    if (tid == 0) {
        float a = b4[0];
        #pragma unroll
        for (int o = 0; o < 16; o++) a = fmaf(s_y[o], W4[o], a);
        out[i] = a;
    }
}

// ---------------------------------------------------------------------------
extern "C" void kernel_launch(void* const* d_in, const int* in_sizes, int n_in,
                              void* d_out, int out_size)
{
    const float* x  = (const float*)d_in[0];
    const float* W  = (const float*)d_in[1];
    const float* W1 = (const float*)d_in[2];
    const float* b1 = (const float*)d_in[3];
    const float* W2 = (const float*)d_in[4];
    const float* W3 = (const float*)d_in[5];
    const float* b3 = (const float*)d_in[6];
    const float* W4 = (const float*)d_in[7];
    const float* b4 = (const float*)d_in[8];
    float* out = (float*)d_out;

    phaseG<<<NN*2, 256>>>(x);
    phaseA<<<GRID_AC, BLK>>>(W);
    phaseB<<<NN, 256>>>(W1, b1, W2);
    phaseC<<<GRID_AC, BLK>>>();
    phaseD<<<NN, 256>>>(W3, b3, W4, b4, out);
}

// round 7
// speedup vs baseline: 1.2155x; 1.2155x over previous
#include <cuda_runtime.h>

#define NN 512
#define RR 16
#define HH 16
#define TI 4               // i-rows per warp
#define JS 16              // j slices (partial buffers)
#define JPW (NN/JS)        // 32 j per slice
#define JCH 8              // j's staged per chunk
#define NCH (JPW/JCH)      // 4 chunks
#define WPB 8              // warps per block
#define BLK 256
#define NIG (NN/TI)        // 128 i-groups
#define GRID_AC ((NIG/WPB)*JS)   // 16*16 = 256 blocks

// smearing constants (f32)
#define SM_START 0.006737946999085467f
#define SM_MSTEP ((1.0f - SM_START) * (1.0f/15.0f))
#define SM_SBETA (0.125f * (1.0f - SM_START))
#define SM_BETA  (1.0f / (SM_SBETA * SM_SBETA))
#define PI_OVER5 0.6283185307179586f

// scratch
__device__ __align__(16) float g_sm[NN*NN*RR];   // [i][j][r]  16MB
__device__ float4 g_diffn4[NN*NN];               // [i][j] -> (d0,d1,d2,0)
__device__ float g_bkp [JS*NN*48];
__device__ float g_bqp [JS*NN*48];
__device__ float g_Sp  [JS*NN*48];
__device__ float g_S   [NN*48];
__device__ float g_lr  [NN*1024];                // left(512)|right(512)
__device__ float g_bk2p[JS*NN*48];
__device__ float g_bq2p[JS*NN*48];

// ---------------------------------------------------------------------------
// Phase G: pair-parallel geometry + smearing. One thread per (i,j).
// ---------------------------------------------------------------------------
__global__ __launch_bounds__(256) void phaseG(const float* __restrict__ x)
{
    const int i = blockIdx.x >> 1;
    const int j = ((blockIdx.x & 1) << 8) + threadIdx.x;

    const float xi0 = __ldg(&x[i*3+0]);
    const float xi1 = __ldg(&x[i*3+1]);
    const float xi2 = __ldg(&x[i*3+2]);
    const float dx = xi0 - __ldg(&x[j*3+0]);
    const float dy = xi1 - __ldg(&x[j*3+1]);
    const float dz = xi2 - __ldg(&x[j*3+2]);

    const float nsq = fmaf(dx,dx, fmaf(dy,dy, fmaf(dz,dz, 1e-6f)));
    const float rin = rsqrtf(nsq);
    const float d   = nsq * rin;
    const float inv = rin * rin;

    g_diffn4[i*NN + j] = make_float4(dx*inv, dy*inv, dz*inv, 0.f);

    const float e   = __expf(-d);
    const float cut = (d < 5.0f) ? 0.5f*(__cosf(d*PI_OVER5) + 1.0f) : 0.0f;

    float4* gp = (float4*)&g_sm[(i*NN + j)*16];
    #pragma unroll
    for (int rg = 0; rg < 4; rg++) {
        float4 v;
        float u0 = e - (SM_START + SM_MSTEP*(float)(rg*4+0));
        float u1 = e - (SM_START + SM_MSTEP*(float)(rg*4+1));
        float u2 = e - (SM_START + SM_MSTEP*(float)(rg*4+2));
        float u3 = e - (SM_START + SM_MSTEP*(float)(rg*4+3));
        v.x = cut * __expf(-SM_BETA*u0*u0);
        v.y = cut * __expf(-SM_BETA*u1*u1);
        v.z = cut * __expf(-SM_BETA*u2*u2);
        v.w = cut * __expf(-SM_BETA*u3*u3);
        gp[rg] = v;
    }
}

// ---------------------------------------------------------------------------
// Phase A: first contraction. Block = (32 i's, j-slice of 32), chunks of 8 j.
// All operands staged cooperatively; inner loop = pure LDS + FMA, no syncs.
// Lanes 0-15 K path (c=lane), 16-31 Q path.
// ---------------------------------------------------------------------------
__global__ __launch_bounds__(BLK, 2) void phaseA(const float* __restrict__ W)
{
    __shared__ __align__(16) float s_W[2*2048 + 16];        // K[2048] pad16 Q
    __shared__ __align__(16) float s_SM[WPB*TI][JCH][16];   // 16KB
    __shared__ __align__(16) float4 s_DF[WPB*TI][JCH];      // 4KB

    const int tid  = threadIdx.x;
    const int w    = tid >> 5;
    const int lane = tid & 31;
    const int igb  = blockIdx.x >> 4;        // / JS
    const int js   = blockIdx.x & (JS-1);
    const int i0b  = igb*(WPB*TI);
    const int c    = lane & 15;
    const bool isQ = lane >= 16;

    float accP[TI][3], accS[TI][3];
    #pragma unroll
    for (int t = 0; t < TI; t++)
        #pragma unroll
        for (int b = 0; b < 3; b++) { accP[t][b] = 0.f; accS[t][b] = 0.f; }

    for (int ch = 0; ch < NCH; ch++) {
        const int j0 = js*JPW + ch*JCH;
        __syncthreads();
        {   // stage K/Q weights: 8 j x 256 floats each
            float4* dst = (float4*)s_W;
            const float4* srcK = (const float4*)(W + j0*256);
            const float4* srcQ = (const float4*)(W + NN*RR*HH + j0*256);
            dst[tid]           = srcK[tid];
            dst[tid + 256]     = srcK[tid + 256];
            dst[516 + tid]     = srcQ[tid];
            dst[516 + tid+256] = srcQ[tid + 256];
        }
        {   // stage sm: 32 i x 8 j x 16 r
            const float4* src = (const float4*)g_sm;
            float4* dst = (float4*)s_SM;
            #pragma unroll
            for (int f = 0; f < 4; f++) {
                int idx = tid + f*256;
                int il = idx >> 5, o = idx & 31;
                dst[il*32 + o] = src[((i0b+il)*NN + j0)*4 + o];
            }
        }
        {   // stage diffn: 32 i x 8 j
            int il = tid >> 3, jl = tid & 7;
            s_DF[il][jl] = g_diffn4[(i0b+il)*NN + j0 + jl];
        }
        __syncthreads();

        #pragma unroll
        for (int jl = 0; jl < JCH; jl++) {
            const float* wp = &s_W[(isQ ? 2064 : 0) + jl*256 + c];
            const float4* sm0 = (const float4*)&s_SM[w*TI+0][jl][0];
            const float4* sm1 = (const float4*)&s_SM[w*TI+1][jl][0];
            const float4* sm2 = (const float4*)&s_SM[w*TI+2][jl][0];
            const float4* sm3 = (const float4*)&s_SM[w*TI+3][jl][0];

            float P0=0.f, P1=0.f, P2=0.f, P3=0.f;
            #pragma unroll
            for (int rg = 0; rg < 4; rg++) {
                float w0 = wp[(rg*4+0)*16];
                float w1 = wp[(rg*4+1)*16];
                float w2 = wp[(rg*4+2)*16];
                float w3 = wp[(rg*4+3)*16];
                float4 a0 = sm0[rg];
                float4 a1 = sm1[rg];
                float4 a2 = sm2[rg];
                float4 a3 = sm3[rg];
                P0 = fmaf(a0.x,w0, fmaf(a0.y,w1, fmaf(a0.z,w2, fmaf(a0.w,w3, P0))));
                P1 = fmaf(a1.x,w0, fmaf(a1.y,w1, fmaf(a1.z,w2, fmaf(a1.w,w3, P1))));
                P2 = fmaf(a2.x,w0, fmaf(a2.y,w1, fmaf(a2.z,w2, fmaf(a2.w,w3, P2))));
                P3 = fmaf(a3.x,w0, fmaf(a3.y,w1, fmaf(a3.z,w2, fmaf(a3.w,w3, P3))));
            }

            float4 df0 = s_DF[w*TI+0][jl];
            float4 df1 = s_DF[w*TI+1][jl];
            float4 df2 = s_DF[w*TI+2][jl];
            float4 df3 = s_DF[w*TI+3][jl];

            accP[0][0] = fmaf(P0, df0.x, accP[0][0]);
            accP[0][1] = fmaf(P0, df0.y, accP[0][1]);
            accP[0][2] = fmaf(P0, df0.z, accP[0][2]);
            accP[1][0] = fmaf(P1, df1.x, accP[1][0]);
            accP[1][1] = fmaf(P1, df1.y, accP[1][1]);
            accP[1][2] = fmaf(P1, df1.z, accP[1][2]);
            accP[2][0] = fmaf(P2, df2.x, accP[2][0]);
            accP[2][1] = fmaf(P2, df2.y, accP[2][1]);
            accP[2][2] = fmaf(P2, df2.z, accP[2][2]);
            accP[3][0] = fmaf(P3, df3.x, accP[3][0]);
            accP[3][1] = fmaf(P3, df3.y, accP[3][1]);
            accP[3][2] = fmaf(P3, df3.z, accP[3][2]);

            if (!isQ) {   // S-term: lane c plays r=c
                float s0 = s_SM[w*TI+0][jl][c];
                float s1 = s_SM[w*TI+1][jl][c];
                float s2 = s_SM[w*TI+2][jl][c];
                float s3 = s_SM[w*TI+3][jl][c];
                accS[0][0] = fmaf(s0, df0.x, accS[0][0]);
                accS[0][1] = fmaf(s0, df0.y, accS[0][1]);
                accS[0][2] = fmaf(s0, df0.z, accS[0][2]);
                accS[1][0] = fmaf(s1, df1.x, accS[1][0]);
                accS[1][1] = fmaf(s1, df1.y, accS[1][1]);
                accS[1][2] = fmaf(s1, df1.z, accS[1][2]);
                accS[2][0] = fmaf(s2, df2.x, accS[2][0]);
                accS[2][1] = fmaf(s2, df2.y, accS[2][1]);
                accS[2][2] = fmaf(s2, df2.z, accS[2][2]);
                accS[3][0] = fmaf(s3, df3.x, accS[3][0]);
                accS[3][1] = fmaf(s3, df3.y, accS[3][1]);
                accS[3][2] = fmaf(s3, df3.z, accS[3][2]);
            }
        }
    }

    const int i0 = i0b + w*TI;
    float* outp = isQ ? g_bqp : g_bkp;
    #pragma unroll
    for (int t = 0; t < TI; t++)
        #pragma unroll
        for (int b = 0; b < 3; b++)
            outp[(js*NN + (i0+t))*48 + c*3 + b] = accP[t][b];
    if (!isQ) {
        #pragma unroll
        for (int t = 0; t < TI; t++)
            #pragma unroll
            for (int b = 0; b < 3; b++)
                g_Sp[(js*NN + (i0+t))*48 + c*3 + b] = accS[t][b];  // c == r
    }
}

// ---------------------------------------------------------------------------
// Phase B: coalesced merge of partials, att outer, MLP1 -> g_lr; merge S.
// ---------------------------------------------------------------------------
__global__ __launch_bounds__(256) void phaseB(const float* __restrict__ W1,
                                              const float* __restrict__ b1,
                                              const float* __restrict__ W2)
{
    const int i = blockIdx.x;
    const int tid = threadIdx.x;
    __shared__ __align__(16) float s_m[3][JS][64];
    __shared__ float s_bk[48], s_bq[48], s_att[256], s_y[16];

    #pragma unroll
    for (int k = 0; k < 3; k++) {
        int idx = tid + k*256;
        if (idx < 3*JS*12) {
            int v = idx / (JS*12), rem = idx % (JS*12);
            int js = rem / 12, f = rem % 12;
            const float4* src = (v == 0) ? (const float4*)g_bkp
                              : (v == 1) ? (const float4*)g_bqp
                                         : (const float4*)g_Sp;
            *(float4*)&s_m[v][js][f*4] = src[(js*NN + i)*12 + f];
        }
    }
    __syncthreads();

    if (tid < 144) {
        int v = tid / 48, e = tid % 48;
        float s = 0.f;
        #pragma unroll
        for (int js = 0; js < JS; js++) s += s_m[v][js][e];
        if (v == 0) s_bk[e] = s;
        else if (v == 1) s_bq[e] = s;
        else g_S[i*48 + e] = s;
    }
    __syncthreads();

    {
        int h = tid >> 4, g = tid & 15;
        s_att[tid] = s_bk[h*3+0]*s_bq[g*3+0] + s_bk[h*3+1]*s_bq[g*3+1]
                   + s_bk[h*3+2]*s_bq[g*3+2];
    }
    __syncthreads();

    {
        int h = tid >> 4, t = tid & 15;
        const float* w = W1 + h*256 + t;
        float p = 0.f;
        #pragma unroll
        for (int q = 0; q < 16; q++) p = fmaf(s_att[t + 16*q], w[16*q], p);
        #pragma unroll
        for (int m = 8; m >= 1; m >>= 1) p += __shfl_xor_sync(0xffffffffu, p, m, 16);
        if (t == 0) {
            float y = p + b1[h];
            s_y[h] = y / (1.0f + __expf(-y));
        }
    }
    __syncthreads();

    #pragma unroll
    for (int q = 0; q < 4; q++) {
        int m = tid + 256*q;
        const float* w = W2 + m*16;
        float a = 0.f;
        #pragma unroll
        for (int o = 0; o < 16; o++) a = fmaf(s_y[o], w[o], a);
        g_lr[i*1024 + m] = a;
    }
}

// ---------------------------------------------------------------------------
// Phase C: second contraction (right-stream). Same staged structure as A.
// ---------------------------------------------------------------------------
__global__ __launch_bounds__(BLK, 2) void phaseC()
{
    __shared__ __align__(16) float s_R[JCH*544];            // 17.4KB
    __shared__ __align__(16) float s_SM[WPB*TI][JCH][16];
    __shared__ __align__(16) float4 s_DF[WPB*TI][JCH];

    const int tid  = threadIdx.x;
    const int w    = tid >> 5;
    const int lane = tid & 31;
    const int igb  = blockIdx.x >> 4;
    const int js   = blockIdx.x & (JS-1);
    const int i0b  = igb*(WPB*TI);
    const int c    = lane & 15;
    const bool isQ = lane >= 16;

    float accP[TI][3];
    #pragma unroll
    for (int t = 0; t < TI; t++)
        #pragma unroll
        for (int b = 0; b < 3; b++) accP[t][b] = 0.f;

    for (int ch = 0; ch < NCH; ch++) {
        const int j0 = js*JPW + ch*JCH;
        __syncthreads();
        {   // stage right half of lr: 8 j x 512 floats (padded rows of 544)
            float4* dst = (float4*)s_R;
            const float4* src = (const float4*)g_lr;
            #pragma unroll
            for (int f = 0; f < 4; f++) {
                int idx = tid + f*256;          // 0..1023
                int jl = idx >> 7, o = idx & 127;
                dst[jl*136 + o + ((o >= 64) ? 4 : 0)] = src[(j0+jl)*256 + 128 + o];
            }
        }
        {   // stage sm
            const float4* src = (const float4*)g_sm;
            float4* dst = (float4*)s_SM;
            #pragma unroll
            for (int f = 0; f < 4; f++) {
                int idx = tid + f*256;
                int il = idx >> 5, o = idx & 31;
                dst[il*32 + o] = src[((i0b+il)*NN + j0)*4 + o];
            }
        }
        {   // stage diffn
            int il = tid >> 3, jl = tid & 7;
            s_DF[il][jl] = g_diffn4[(i0b+il)*NN + j0 + jl];
        }
        __syncthreads();

        #pragma unroll
        for (int jl = 0; jl < JCH; jl++) {
            const float* wp = &s_R[jl*544 + (isQ ? 272 : 0) + c];
            const float4* sm0 = (const float4*)&s_SM[w*TI+0][jl][0];
            const float4* sm1 = (const float4*)&s_SM[w*TI+1][jl][0];
            const float4* sm2 = (const float4*)&s_SM[w*TI+2][jl][0];
            const float4* sm3 = (const float4*)&s_SM[w*TI+3][jl][0];

            float P0=0.f, P1=0.f, P2=0.f, P3=0.f;
            #pragma unroll
            for (int rg = 0; rg < 4; rg++) {
                float w0 = wp[(rg*4+0)*16];
                float w1 = wp[(rg*4+1)*16];
                float w2 = wp[(rg*4+2)*16];
                float w3 = wp[(rg*4+3)*16];
                float4 a0 = sm0[rg];
                float4 a1 = sm1[rg];
                float4 a2 = sm2[rg];
                float4 a3 = sm3[rg];
                P0 = fmaf(a0.x,w0, fmaf(a0.y,w1, fmaf(a0.z,w2, fmaf(a0.w,w3, P0))));
                P1 = fmaf(a1.x,w0, fmaf(a1.y,w1, fmaf(a1.z,w2, fmaf(a1.w,w3, P1))));
                P2 = fmaf(a2.x,w0, fmaf(a2.y,w1, fmaf(a2.z,w2, fmaf(a2.w,w3, P2))));
                P3 = fmaf(a3.x,w0, fmaf(a3.y,w1, fmaf(a3.z,w2, fmaf(a3.w,w3, P3))));
            }

            float4 df0 = s_DF[w*TI+0][jl];
            float4 df1 = s_DF[w*TI+1][jl];
            float4 df2 = s_DF[w*TI+2][jl];
            float4 df3 = s_DF[w*TI+3][jl];

            accP[0][0] = fmaf(P0, df0.x, accP[0][0]);
            accP[0][1] = fmaf(P0, df0.y, accP[0][1]);
            accP[0][2] = fmaf(P0, df0.z, accP[0][2]);
            accP[1][0] = fmaf(P1, df1.x, accP[1][0]);
            accP[1][1] = fmaf(P1, df1.y, accP[1][1]);
            accP[1][2] = fmaf(P1, df1.z, accP[1][2]);
            accP[2][0] = fmaf(P2, df2.x, accP[2][0]);
            accP[2][1] = fmaf(P2, df2.y, accP[2][1]);
            accP[2][2] = fmaf(P2, df2.z, accP[2][2]);
            accP[3][0] = fmaf(P3, df3.x, accP[3][0]);
            accP[3][1] = fmaf(P3, df3.y, accP[3][1]);
            accP[3][2] = fmaf(P3, df3.z, accP[3][2]);
        }
    }

    const int i0 = i0b + w*TI;
    float* outp = isQ ? g_bq2p : g_bk2p;
    #pragma unroll
    for (int t = 0; t < TI; t++)
        #pragma unroll
        for (int b = 0; b < 3; b++)
            outp[(js*NN + (i0+t))*48 + c*3 + b] = accP[t][b];
}

// ---------------------------------------------------------------------------
// Phase D: coalesced merge + left⊗S term, att outer, MLP2, output.
// ---------------------------------------------------------------------------
__global__ __launch_bounds__(256) void phaseD(const float* __restrict__ W3,
                                              const float* __restrict__ b3,
                                              const float* __restrict__ W4,
                                              const float* __restrict__ b4,
                                              float* __restrict__ out)
{
    const int i = blockIdx.x;
    const int tid = threadIdx.x;
    __shared__ __align__(16) float s_m[2][JS][64];
    __shared__ float s_bk[48], s_bq[48], s_att[256], s_y[16];

    #pragma unroll
    for (int k = 0; k < 2; k++) {
        int idx = tid + k*256;
        if (idx < 2*JS*12) {
            int v = idx / (JS*12), rem = idx % (JS*12);
            int js = rem / 12, f = rem % 12;
            const float4* src = (v == 0) ? (const float4*)g_bk2p
                                         : (const float4*)g_bq2p;
            *(float4*)&s_m[v][js][f*4] = src[(js*NN + i)*12 + f];
        }
    }
    __syncthreads();

    if (tid < 96) {
        int v = tid / 48, e = tid % 48;
        int cc = e / 3, b = e % 3;
        float s = 0.f;
        #pragma unroll
        for (int js = 0; js < JS; js++) s += s_m[v][js][e];
        const float* lp = g_lr + i*1024 + (v ? 256 : 0) + cc;
        const float* sp = g_S  + i*48 + b;
        #pragma unroll
        for (int r = 0; r < 16; r++) s = fmaf(lp[r*16], sp[r*3], s);
        if (v == 0) s_bk[e] = s; else s_bq[e] = s;
    }
    __syncthreads();

    {
        int h = tid >> 4, g = tid & 15;
        s_att[tid] = s_bk[h*3+0]*s_bq[g*3+0] + s_bk[h*3+1]*s_bq[g*3+1]
                   + s_bk[h*3+2]*s_bq[g*3+2];
    }
    __syncthreads();

    {
        int h = tid >> 4, t = tid & 15;
        const float* w = W3 + h*256 + t;
        float p = 0.f;
        #pragma unroll
        for (int q = 0; q < 16; q++) p = fmaf(s_att[t + 16*q], w[16*q], p);
        #pragma unroll
        for (int m = 8; m >= 1; m >>= 1) p += __shfl_xor_sync(0xffffffffu, p, m, 16);
        if (t == 0) {
            float y = p + b3[h];
            s_y[h] = y / (1.0f + __expf(-y));
        }
    }
    __syncthreads();

    if (tid == 0) {
        float a = b4[0];
        #pragma unroll
        for (int o = 0; o < 16; o++) a = fmaf(s_y[o], W4[o], a);
        out[i] = a;
    }
}

// ---------------------------------------------------------------------------
extern "C" void kernel_launch(void* const* d_in, const int* in_sizes, int n_in,
                              void* d_out, int out_size)
{
    const float* x  = (const float*)d_in[0];
    const float* W  = (const float*)d_in[1];
    const float* W1 = (const float*)d_in[2];
    const float* b1 = (const float*)d_in[3];
    const float* W2 = (const float*)d_in[4];
    const float* W3 = (const float*)d_in[5];
    const float* b3 = (const float*)d_in[6];
    const float* W4 = (const float*)d_in[7];
    const float* b4 = (const float*)d_in[8];
    float* out = (float*)d_out;

    phaseG<<<NN*2, 256>>>(x);
    phaseA<<<GRID_AC, BLK>>>(W);
    phaseB<<<NN, 256>>>(W1, b1, W2);
    phaseC<<<GRID_AC, BLK>>>();
    phaseD<<<NN, 256>>>(W3, b3, W4, b4, out);
}

// round 9
// speedup vs baseline: 1.2506x; 1.0288x over previous
#include <cuda_runtime.h>

#define NN 512
#define RR 16
#define HH 16
#define TI 4               // i-rows per warp (contraction)
#define JS 16              // j slices (partial buffers)
#define JPW (NN/JS)        // 32 j per slice
#define JCH 8              // j's per chunk (8 warps = 8 j in pair-gen)
#define NCH (JPW/JCH)      // 4 chunks
#define WPB 8
#define BLK 256
#define NIG (NN/TI)
#define GRID_AC ((NN/32)*JS)     // 16 i-blocks * 16 slices = 256 blocks

// smearing constants (f32)
#define SM_START 0.006737946999085467f
#define SM_MSTEP ((1.0f - SM_START) * (1.0f/15.0f))
#define SM_SBETA (0.125f * (1.0f - SM_START))
#define SM_BETA  (1.0f / (SM_SBETA * SM_SBETA))
#define PI_OVER5 0.6283185307179586f

// scratch (small only — no pair tensors)
__device__ float g_bkp [JS*NN*48];
__device__ float g_bqp [JS*NN*48];
__device__ float g_Sp  [JS*NN*48];
__device__ float g_S   [NN*48];
__device__ float g_lr  [NN*1024];                // left(512)|right(512)
__device__ float g_bk2p[JS*NN*48];
__device__ float g_bq2p[JS*NN*48];

// ---------------------------------------------------------------------------
// In-place pair generation: thread (il=lane, jl=warp) computes pair
// (i0b+lane, j0+w): diffn float4 + 16 smearing values -> smem.
// ---------------------------------------------------------------------------
__device__ __forceinline__ void gen_pair(const float* s_x, int ip, int jp,
                                         float4 (*s_SM4)[JCH][32],
                                         float4 (*s_DF)[32],
                                         int w, int lane)
{
    const float dx = s_x[ip*3+0] - s_x[jp*3+0];
    const float dy = s_x[ip*3+1] - s_x[jp*3+1];
    const float dz = s_x[ip*3+2] - s_x[jp*3+2];
    const float nsq = fmaf(dx,dx, fmaf(dy,dy, fmaf(dz,dz, 1e-6f)));
    const float rin = rsqrtf(nsq);
    const float d   = nsq * rin;
    const float inv = rin * rin;
    s_DF[w][lane] = make_float4(dx*inv, dy*inv, dz*inv, 0.f);

    const float e   = __expf(-d);
    const float cut = (d < 5.0f) ? 0.5f*(__cosf(d*PI_OVER5) + 1.0f) : 0.0f;
    #pragma unroll
    for (int rg = 0; rg < 4; rg++) {
        float u0 = e - (SM_START + SM_MSTEP*(float)(rg*4+0));
        float u1 = e - (SM_START + SM_MSTEP*(float)(rg*4+1));
        float u2 = e - (SM_START + SM_MSTEP*(float)(rg*4+2));
        float u3 = e - (SM_START + SM_MSTEP*(float)(rg*4+3));
        float4 v;
        v.x = cut * __expf(-SM_BETA*u0*u0);
        v.y = cut * __expf(-SM_BETA*u1*u1);
        v.z = cut * __expf(-SM_BETA*u2*u2);
        v.w = cut * __expf(-SM_BETA*u3*u3);
        s_SM4[rg][w][lane] = v;
    }
}

// ---------------------------------------------------------------------------
// Phase A: first contraction, pairs recomputed in place. No pair scratch.
// Block = (32 i's, j-slice of 32). Lanes 0-15 K (c=lane), 16-31 Q.
// ---------------------------------------------------------------------------
__global__ __launch_bounds__(BLK, 2) void phaseA(const float* __restrict__ x,
                                                 const float* __restrict__ W)
{
    __shared__ float s_x[NN*3];
    __shared__ __align__(16) float s_W[2*JCH*256 + 16];   // K[2048] pad16 Q[2048]
    __shared__ __align__(16) float4 s_SM4[4][JCH][32];    // [rg][jl][il]
    __shared__ __align__(16) float4 s_DF[JCH][32];        // [jl][il]

    const int tid  = threadIdx.x;
    const int w    = tid >> 5;
    const int lane = tid & 31;
    const int igb  = blockIdx.x >> 4;
    const int js   = blockIdx.x & (JS-1);
    const int i0b  = igb*32;
    const int c    = lane & 15;
    const bool isQ = lane >= 16;
    const int ip   = i0b + lane;      // pair-gen i (this thread)

    for (int k = tid; k < NN*3; k += BLK) s_x[k] = x[k];

    float accP[TI][3], accS[TI][3];
    #pragma unroll
    for (int t = 0; t < TI; t++)
        #pragma unroll
        for (int b = 0; b < 3; b++) { accP[t][b] = 0.f; accS[t][b] = 0.f; }

    __syncthreads();

    for (int ch = 0; ch < NCH; ch++) {
        const int j0 = js*JPW + ch*JCH;
        if (ch) __syncthreads();                   // prev chunk consumed
        {   // stage weights: 8 j x 256 floats, K and Q
            float4* dst = (float4*)s_W;
            const float4* srcK = (const float4*)(W + j0*256);
            const float4* srcQ = (const float4*)(W + NN*RR*HH + j0*256);
            dst[tid]             = srcK[tid];
            dst[tid + 256]       = srcK[tid + 256];
            dst[516 + tid]       = srcQ[tid];
            dst[516 + tid + 256] = srcQ[tid + 256];
        }
        gen_pair(s_x, ip, j0 + w, s_SM4, s_DF, w, lane);
        __syncthreads();

        #pragma unroll
        for (int jl = 0; jl < JCH; jl++) {
            const float* wp = &s_W[(isQ ? 2064 : 0) + jl*256 + c];
            float P0=0.f, P1=0.f, P2=0.f, P3=0.f;
            #pragma unroll
            for (int rg = 0; rg < 4; rg++) {
                float w0 = wp[(rg*4+0)*16];
                float w1 = wp[(rg*4+1)*16];
                float w2 = wp[(rg*4+2)*16];
                float w3 = wp[(rg*4+3)*16];
                float4 a0 = s_SM4[rg][jl][w*TI+0];
                float4 a1 = s_SM4[rg][jl][w*TI+1];
                float4 a2 = s_SM4[rg][jl][w*TI+2];
                float4 a3 = s_SM4[rg][jl][w*TI+3];
                P0 = fmaf(a0.x,w0, fmaf(a0.y,w1, fmaf(a0.z,w2, fmaf(a0.w,w3, P0))));
                P1 = fmaf(a1.x,w0, fmaf(a1.y,w1, fmaf(a1.z,w2, fmaf(a1.w,w3, P1))));
                P2 = fmaf(a2.x,w0, fmaf(a2.y,w1, fmaf(a2.z,w2, fmaf(a2.w,w3, P2))));
                P3 = fmaf(a3.x,w0, fmaf(a3.y,w1, fmaf(a3.z,w2, fmaf(a3.w,w3, P3))));
            }

            float4 df0 = s_DF[jl][w*TI+0];
            float4 df1 = s_DF[jl][w*TI+1];
            float4 df2 = s_DF[jl][w*TI+2];
            float4 df3 = s_DF[jl][w*TI+3];

            accP[0][0] = fmaf(P0, df0.x, accP[0][0]);
            accP[0][1] = fmaf(P0, df0.y, accP[0][1]);
            accP[0][2] = fmaf(P0, df0.z, accP[0][2]);
            accP[1][0] = fmaf(P1, df1.x, accP[1][0]);
            accP[1][1] = fmaf(P1, df1.y, accP[1][1]);
            accP[1][2] = fmaf(P1, df1.z, accP[1][2]);
            accP[2][0] = fmaf(P2, df2.x, accP[2][0]);
            accP[2][1] = fmaf(P2, df2.y, accP[2][1]);
            accP[2][2] = fmaf(P2, df2.z, accP[2][2]);
            accP[3][0] = fmaf(P3, df3.x, accP[3][0]);
            accP[3][1] = fmaf(P3, df3.y, accP[3][1]);
            accP[3][2] = fmaf(P3, df3.z, accP[3][2]);

            if (!isQ) {   // S-term: lane c plays r=c (scalar picks, 4-way conflict ok)
                float s0 = ((const float*)&s_SM4[c>>2][jl][w*TI+0])[c&3];
                float s1 = ((const float*)&s_SM4[c>>2][jl][w*TI+1])[c&3];
                float s2 = ((const float*)&s_SM4[c>>2][jl][w*TI+2])[c&3];
                float s3 = ((const float*)&s_SM4[c>>2][jl][w*TI+3])[c&3];
                accS[0][0] = fmaf(s0, df0.x, accS[0][0]);
                accS[0][1] = fmaf(s0, df0.y, accS[0][1]);
                accS[0][2] = fmaf(s0, df0.z, accS[0][2]);
                accS[1][0] = fmaf(s1, df1.x, accS[1][0]);
                accS[1][1] = fmaf(s1, df1.y, accS[1][1]);
                accS[1][2] = fmaf(s1, df1.z, accS[1][2]);
                accS[2][0] = fmaf(s2, df2.x, accS[2][0]);
                accS[2][1] = fmaf(s2, df2.y, accS[2][1]);
                accS[2][2] = fmaf(s2, df2.z, accS[2][2]);
                accS[3][0] = fmaf(s3, df3.x, accS[3][0]);
                accS[3][1] = fmaf(s3, df3.y, accS[3][1]);
                accS[3][2] = fmaf(s3, df3.z, accS[3][2]);
            }
        }
    }

    const int i0 = i0b + w*TI;
    float* outp = isQ ? g_bqp : g_bkp;
    #pragma unroll
    for (int t = 0; t < TI; t++)
        #pragma unroll
        for (int b = 0; b < 3; b++)
            outp[(js*NN + (i0+t))*48 + c*3 + b] = accP[t][b];
    if (!isQ) {
        #pragma unroll
        for (int t = 0; t < TI; t++)
            #pragma unroll
            for (int b = 0; b < 3; b++)
                g_Sp[(js*NN + (i0+t))*48 + c*3 + b] = accS[t][b];  // c == r
    }
}

// ---------------------------------------------------------------------------
// Phase B: coalesced merge of partials, att outer, MLP1 -> g_lr; merge S.
// ---------------------------------------------------------------------------
__global__ __launch_bounds__(256) void phaseB(const float* __restrict__ W1,
                                              const float* __restrict__ b1,
                                              const float* __restrict__ W2)
{
    const int i = blockIdx.x;
    const int tid = threadIdx.x;
    __shared__ __align__(16) float s_m[3][JS][64];
    __shared__ float s_bk[48], s_bq[48], s_att[256], s_y[16];

    #pragma unroll
    for (int k = 0; k < 3; k++) {
        int idx = tid + k*256;
        if (idx < 3*JS*12) {
            int v = idx / (JS*12), rem = idx % (JS*12);
            int js = rem / 12, f = rem % 12;
            const float4* src = (v == 0) ? (const float4*)g_bkp
                              : (v == 1) ? (const float4*)g_bqp
                                         : (const float4*)g_Sp;
            *(float4*)&s_m[v][js][f*4] = src[(js*NN + i)*12 + f];
        }
    }
    __syncthreads();

    if (tid < 144) {
        int v = tid / 48, e = tid % 48;
        float s = 0.f;
        #pragma unroll
        for (int js = 0; js < JS; js++) s += s_m[v][js][e];
        if (v == 0) s_bk[e] = s;
        else if (v == 1) s_bq[e] = s;
        else g_S[i*48 + e] = s;
    }
    __syncthreads();

    {
        int h = tid >> 4, g = tid & 15;
        s_att[tid] = s_bk[h*3+0]*s_bq[g*3+0] + s_bk[h*3+1]*s_bq[g*3+1]
                   + s_bk[h*3+2]*s_bq[g*3+2];
    }
    __syncthreads();

    {
        int h = tid >> 4, t = tid & 15;
        const float* w = W1 + h*256 + t;
        float p = 0.f;
        #pragma unroll
        for (int q = 0; q < 16; q++) p = fmaf(s_att[t + 16*q], w[16*q], p);
        #pragma unroll
        for (int m = 8; m >= 1; m >>= 1) p += __shfl_xor_sync(0xffffffffu, p, m, 16);
        if (t == 0) {
            float y = p + b1[h];
            s_y[h] = y / (1.0f + __expf(-y));
        }
    }
    __syncthreads();

    #pragma unroll
    for (int q = 0; q < 4; q++) {
        int m = tid + 256*q;
        const float* w = W2 + m*16;
        float a = 0.f;
        #pragma unroll
        for (int o = 0; o < 16; o++) a = fmaf(s_y[o], w[o], a);
        g_lr[i*1024 + m] = a;
    }
}

// ---------------------------------------------------------------------------
// Phase C: second contraction (right-stream), pairs recomputed in place.
// ---------------------------------------------------------------------------
__global__ __launch_bounds__(BLK, 2) void phaseC(const float* __restrict__ x)
{
    __shared__ float s_x[NN*3];
    __shared__ __align__(16) float s_R[JCH*544];          // 17.4KB (K|pad|Q rows)
    __shared__ __align__(16) float4 s_SM4[4][JCH][32];
    __shared__ __align__(16) float4 s_DF[JCH][32];

    const int tid  = threadIdx.x;
    const int w    = tid >> 5;
    const int lane = tid & 31;
    const int igb  = blockIdx.x >> 4;
    const int js   = blockIdx.x & (JS-1);
    const int i0b  = igb*32;
    const int c    = lane & 15;
    const bool isQ = lane >= 16;
    const int ip   = i0b + lane;

    for (int k = tid; k < NN*3; k += BLK) s_x[k] = x[k];

    float accP[TI][3];
    #pragma unroll
    for (int t = 0; t < TI; t++)
        #pragma unroll
        for (int b = 0; b < 3; b++) accP[t][b] = 0.f;

    __syncthreads();

    for (int ch = 0; ch < NCH; ch++) {
        const int j0 = js*JPW + ch*JCH;
        if (ch) __syncthreads();
        {   // stage right half of lr: 8 j x 512 floats (padded rows of 544)
            float4* dst = (float4*)s_R;
            const float4* src = (const float4*)g_lr;
            #pragma unroll
            for (int f = 0; f < 4; f++) {
                int idx = tid + f*256;
                int jl = idx >> 7, o = idx & 127;
                dst[jl*136 + o + ((o >= 64) ? 4 : 0)] = src[(j0+jl)*256 + 128 + o];
            }
        }
        gen_pair(s_x, ip, j0 + w, s_SM4, s_DF, w, lane);
        __syncthreads();

        #pragma unroll
        for (int jl = 0; jl < JCH; jl++) {
            const float* wp = &s_R[jl*544 + (isQ ? 272 : 0) + c];
            float P0=0.f, P1=0.f, P2=0.f, P3=0.f;
            #pragma unroll
            for (int rg = 0; rg < 4; rg++) {
                float w0 = wp[(rg*4+0)*16];
                float w1 = wp[(rg*4+1)*16];
                float w2 = wp[(rg*4+2)*16];
                float w3 = wp[(rg*4+3)*16];
                float4 a0 = s_SM4[rg][jl][w*TI+0];
                float4 a1 = s_SM4[rg][jl][w*TI+1];
                float4 a2 = s_SM4[rg][jl][w*TI+2];
                float4 a3 = s_SM4[rg][jl][w*TI+3];
                P0 = fmaf(a0.x,w0, fmaf(a0.y,w1, fmaf(a0.z,w2, fmaf(a0.w,w3, P0))));
                P1 = fmaf(a1.x,w0, fmaf(a1.y,w1, fmaf(a1.z,w2, fmaf(a1.w,w3, P1))));
                P2 = fmaf(a2.x,w0, fmaf(a2.y,w1, fmaf(a2.z,w2, fmaf(a2.w,w3, P2))));
                P3 = fmaf(a3.x,w0, fmaf(a3.y,w1, fmaf(a3.z,w2, fmaf(a3.w,w3, P3))));
            }

            float4 df0 = s_DF[jl][w*TI+0];
            float4 df1 = s_DF[jl][w*TI+1];
            float4 df2 = s_DF[jl][w*TI+2];
            float4 df3 = s_DF[jl][w*TI+3];

            accP[0][0] = fmaf(P0, df0.x, accP[0][0]);
            accP[0][1] = fmaf(P0, df0.y, accP[0][1]);
            accP[0][2] = fmaf(P0, df0.z, accP[0][2]);
            accP[1][0] = fmaf(P1, df1.x, accP[1][0]);
            accP[1][1] = fmaf(P1, df1.y, accP[1][1]);
            accP[1][2] = fmaf(P1, df1.z, accP[1][2]);
            accP[2][0] = fmaf(P2, df2.x, accP[2][0]);
            accP[2][1] = fmaf(P2, df2.y, accP[2][1]);
            accP[2][2] = fmaf(P2, df2.z, accP[2][2]);
            accP[3][0] = fmaf(P3, df3.x, accP[3][0]);
            accP[3][1] = fmaf(P3, df3.y, accP[3][1]);
            accP[3][2] = fmaf(P3, df3.z, accP[3][2]);
        }
    }

    const int i0 = i0b + w*TI;
    float* outp = isQ ? g_bq2p : g_bk2p;
    #pragma unroll
    for (int t = 0; t < TI; t++)
        #pragma unroll
        for (int b = 0; b < 3; b++)
            outp[(js*NN + (i0+t))*48 + c*3 + b] = accP[t][b];
}

// ---------------------------------------------------------------------------
// Phase D: coalesced merge + left⊗S term, att outer, MLP2, output.
// ---------------------------------------------------------------------------
__global__ __launch_bounds__(256) void phaseD(const float* __restrict__ W3,
                                              const float* __restrict__ b3,
                                              const float* __restrict__ W4,
                                              const float* __restrict__ b4,
                                              float* __restrict__ out)
{
    const int i = blockIdx.x;
    const int tid = threadIdx.x;
    __shared__ __align__(16) float s_m[2][JS][64];
    __shared__ float s_bk[48], s_bq[48], s_att[256], s_y[16];

    #pragma unroll
    for (int k = 0; k < 2; k++) {
        int idx = tid + k*256;
        if (idx < 2*JS*12) {
            int v = idx / (JS*12), rem = idx % (JS*12);
            int js = rem / 12, f = rem % 12;
            const float4* src = (v == 0) ? (const float4*)g_bk2p
                                         : (const float4*)g_bq2p;
            *(float4*)&s_m[v][js][f*4] = src[(js*NN + i)*12 + f];
        }
    }
    __syncthreads();

    if (tid < 96) {
        int v = tid / 48, e = tid % 48;
        int cc = e / 3, b = e % 3;
        float s = 0.f;
        #pragma unroll
        for (int js = 0; js < JS; js++) s += s_m[v][js][e];
        const float* lp = g_lr + i*1024 + (v ? 256 : 0) + cc;
        const float* sp = g_S  + i*48 + b;
        #pragma unroll
        for (int r = 0; r < 16; r++) s = fmaf(lp[r*16], sp[r*3], s);
        if (v == 0) s_bk[e] = s; else s_bq[e] = s;
    }
    __syncthreads();

    {
        int h = tid >> 4, g = tid & 15;
        s_att[tid] = s_bk[h*3+0]*s_bq[g*3+0] + s_bk[h*3+1]*s_bq[g*3+1]
                   + s_bk[h*3+2]*s_bq[g*3+2];
    }
    __syncthreads();

    {
        int h = tid >> 4, t = tid & 15;
        const float* w = W3 + h*256 + t;
        float p = 0.f;
        #pragma unroll
        for (int q = 0; q < 16; q++) p = fmaf(s_att[t + 16*q], w[16*q], p);
        #pragma unroll
        for (int m = 8; m >= 1; m >>= 1) p += __shfl_xor_sync(0xffffffffu, p, m, 16);
        if (t == 0) {
            float y = p + b3[h];
            s_y[h] = y / (1.0f + __expf(-y));
        }
    }
    __syncthreads();

    if (tid == 0) {
        float a = b4[0];
        #pragma unroll
        for (int o = 0; o < 16; o++) a = fmaf(s_y[o], W4[o], a);
        out[i] = a;
    }
}

// ---------------------------------------------------------------------------
extern "C" void kernel_launch(void* const* d_in, const int* in_sizes, int n_in,
                              void* d_out, int out_size)
{
    const float* x  = (const float*)d_in[0];
    const float* W  = (const float*)d_in[1];
    const float* W1 = (const float*)d_in[2];
    const float* b1 = (const float*)d_in[3];
    const float* W2 = (const float*)d_in[4];
    const float* W3 = (const float*)d_in[5];
    const float* b3 = (const float*)d_in[6];
    const float* W4 = (const float*)d_in[7];
    const float* b4 = (const float*)d_in[8];
    float* out = (float*)d_out;

    phaseA<<<GRID_AC, BLK>>>(x, W);
    phaseB<<<NN, 256>>>(W1, b1, W2);
    phaseC<<<GRID_AC, BLK>>>(x);
    phaseD<<<NN, 256>>>(W3, b3, W4, b4, out);
}

// round 12
// speedup vs baseline: 1.2663x; 1.0126x over previous
#include <cuda_runtime.h>

#define NN 512
#define RR 16
#define HH 16
#define TI 4               // i-rows per warp (contraction)
#define JS 16              // j slices (partial buffers)
#define JPW (NN/JS)        // 32 j per slice
#define JCH 8              // j's per chunk (8 warps = 8 j in pair-gen)
#define NCH (JPW/JCH)      // 4 chunks
#define WPB 8
#define BLK 256
#define GRID_AC ((NN/32)*JS)     // 16 i-blocks * 16 slices = 256 blocks

// smearing constants (f32)
#define SM_START 0.006737946999085467f
#define SM_MSTEP ((1.0f - SM_START) * (1.0f/15.0f))
#define SM_SBETA (0.125f * (1.0f - SM_START))
#define SM_BETA  (1.0f / (SM_SBETA * SM_SBETA))
#define PI_OVER5 0.6283185307179586f

// scratch (small only — no pair tensors)
__device__ float g_bkp [JS*NN*48];
__device__ float g_bqp [JS*NN*48];
__device__ float g_Sp  [JS*NN*48];
__device__ float g_S   [NN*48];
__device__ float g_lr  [NN*1024];                // left(512)|right(512)
__device__ float g_bk2p[JS*NN*48];
__device__ float g_bq2p[JS*NN*48];

// ---------------------------------------------------------------------------
// In-place pair generation: thread (il=lane, jl=warp) computes pair
// (i0b+lane, j0+w): diffn float4 + 16 smearing values -> smem.
// s_xi: 32 i-rows (local), s_xj: 32 j-rows of this slice (local).
// ---------------------------------------------------------------------------
__device__ __forceinline__ void gen_pair(const float* s_xi, const float* s_xj,
                                         int il, int jl,
                                         float4 (*s_SM4)[JCH][32],
                                         float4 (*s_DF)[32],
                                         int w, int lane)
{
    const float dx = s_xi[il*3+0] - s_xj[jl*3+0];
    const float dy = s_xi[il*3+1] - s_xj[jl*3+1];
    const float dz = s_xi[il*3+2] - s_xj[jl*3+2];
    const float nsq = fmaf(dx,dx, fmaf(dy,dy, fmaf(dz,dz, 1e-6f)));
    const float rin = rsqrtf(nsq);
    const float d   = nsq * rin;
    const float inv = rin * rin;
    s_DF[w][lane] = make_float4(dx*inv, dy*inv, dz*inv, 0.f);

    const float e   = __expf(-d);
    const float cut = (d < 5.0f) ? 0.5f*(__cosf(d*PI_OVER5) + 1.0f) : 0.0f;
    #pragma unroll
    for (int rg = 0; rg < 4; rg++) {
        float u0 = e - (SM_START + SM_MSTEP*(float)(rg*4+0));
        float u1 = e - (SM_START + SM_MSTEP*(float)(rg*4+1));
        float u2 = e - (SM_START + SM_MSTEP*(float)(rg*4+2));
        float u3 = e - (SM_START + SM_MSTEP*(float)(rg*4+3));
        float4 v;
        v.x = cut * __expf(-SM_BETA*u0*u0);
        v.y = cut * __expf(-SM_BETA*u1*u1);
        v.z = cut * __expf(-SM_BETA*u2*u2);
        v.w = cut * __expf(-SM_BETA*u3*u3);
        s_SM4[rg][w][lane] = v;
    }
}

// ---------------------------------------------------------------------------
// Phase A: first contraction, pairs recomputed in place.
// Block = (32 i's, j-slice of 32). Lanes 0-15 K (c=lane), 16-31 Q.
// ---------------------------------------------------------------------------
__global__ __launch_bounds__(BLK, 3) void phaseA(const float* __restrict__ x,
                                                 const float* __restrict__ W)
{
    __shared__ float s_xi[96], s_xj[96];
    __shared__ __align__(16) float s_W[2*JCH*256 + 16];   // K[2048] pad16 Q[2048]
    __shared__ __align__(16) float4 s_SM4[4][JCH][32];    // [rg][jl][il]
    __shared__ __align__(16) float4 s_DF[JCH][32];        // [jl][il]

    const int tid  = threadIdx.x;
    const int w    = tid >> 5;
    const int lane = tid & 31;
    const int igb  = blockIdx.x >> 4;
    const int js   = blockIdx.x & (JS-1);
    const int i0b  = igb*32;
    const int c    = lane & 15;
    const bool isQ = lane >= 16;

    if (tid < 96)            s_xi[tid]    = x[i0b*3 + tid];
    else if (tid < 192)      s_xj[tid-96] = x[js*JPW*3 + (tid-96)];

    float accP[TI][3], accS[TI][3];
    #pragma unroll
    for (int t = 0; t < TI; t++)
        #pragma unroll
        for (int b = 0; b < 3; b++) { accP[t][b] = 0.f; accS[t][b] = 0.f; }

    __syncthreads();

    for (int ch = 0; ch < NCH; ch++) {
        const int j0 = js*JPW + ch*JCH;
        if (ch) __syncthreads();                   // prev chunk consumed
        {   // stage weights: 8 j x 256 floats, K and Q
            float4* dst = (float4*)s_W;
            const float4* srcK = (const float4*)(W + j0*256);
            const float4* srcQ = (const float4*)(W + NN*RR*HH + j0*256);
            dst[tid]             = srcK[tid];
            dst[tid + 256]       = srcK[tid + 256];
            dst[516 + tid]       = srcQ[tid];
            dst[516 + tid + 256] = srcQ[tid + 256];
        }
        gen_pair(s_xi, s_xj, lane, ch*JCH + w, s_SM4, s_DF, w, lane);
        __syncthreads();

        #pragma unroll 4
        for (int jl = 0; jl < JCH; jl++) {
            const float* wp = &s_W[(isQ ? 2064 : 0) + jl*256 + c];
            float P0=0.f, P1=0.f, P2=0.f, P3=0.f;
            #pragma unroll
            for (int rg = 0; rg < 4; rg++) {
                float w0 = wp[(rg*4+0)*16];
                float w1 = wp[(rg*4+1)*16];
                float w2 = wp[(rg*4+2)*16];
                float w3 = wp[(rg*4+3)*16];
                float4 a0 = s_SM4[rg][jl][w*TI+0];
                float4 a1 = s_SM4[rg][jl][w*TI+1];
                float4 a2 = s_SM4[rg][jl][w*TI+2];
                float4 a3 = s_SM4[rg][jl][w*TI+3];
                P0 = fmaf(a0.x,w0, fmaf(a0.y,w1, fmaf(a0.z,w2, fmaf(a0.w,w3, P0))));
                P1 = fmaf(a1.x,w0, fmaf(a1.y,w1, fmaf(a1.z,w2, fmaf(a1.w,w3, P1))));
                P2 = fmaf(a2.x,w0, fmaf(a2.y,w1, fmaf(a2.z,w2, fmaf(a2.w,w3, P2))));
                P3 = fmaf(a3.x,w0, fmaf(a3.y,w1, fmaf(a3.z,w2, fmaf(a3.w,w3, P3))));
            }

            float4 df0 = s_DF[jl][w*TI+0];
            float4 df1 = s_DF[jl][w*TI+1];
            float4 df2 = s_DF[jl][w*TI+2];
            float4 df3 = s_DF[jl][w*TI+3];

            accP[0][0] = fmaf(P0, df0.x, accP[0][0]);
            accP[0][1] = fmaf(P0, df0.y, accP[0][1]);
            accP[0][2] = fmaf(P0, df0.z, accP[0][2]);
            accP[1][0] = fmaf(P1, df1.x, accP[1][0]);
            accP[1][1] = fmaf(P1, df1.y, accP[1][1]);
            accP[1][2] = fmaf(P1, df1.z, accP[1][2]);
            accP[2][0] = fmaf(P2, df2.x, accP[2][0]);
            accP[2][1] = fmaf(P2, df2.y, accP[2][1]);
            accP[2][2] = fmaf(P2, df2.z, accP[2][2]);
            accP[3][0] = fmaf(P3, df3.x, accP[3][0]);
            accP[3][1] = fmaf(P3, df3.y, accP[3][1]);
            accP[3][2] = fmaf(P3, df3.z, accP[3][2]);

            if (!isQ) {   // S-term: lane c plays r=c (scalar picks)
                float s0 = ((const float*)&s_SM4[c>>2][jl][w*TI+0])[c&3];
                float s1 = ((const float*)&s_SM4[c>>2][jl][w*TI+1])[c&3];
                float s2 = ((const float*)&s_SM4[c>>2][jl][w*TI+2])[c&3];
                float s3 = ((const float*)&s_SM4[c>>2][jl][w*TI+3])[c&3];
                accS[0][0] = fmaf(s0, df0.x, accS[0][0]);
                accS[0][1] = fmaf(s0, df0.y, accS[0][1]);
                accS[0][2] = fmaf(s0, df0.z, accS[0][2]);
                accS[1][0] = fmaf(s1, df1.x, accS[1][0]);
                accS[1][1] = fmaf(s1, df1.y, accS[1][1]);
                accS[1][2] = fmaf(s1, df1.z, accS[1][2]);
                accS[2][0] = fmaf(s2, df2.x, accS[2][0]);
                accS[2][1] = fmaf(s2, df2.y, accS[2][1]);
                accS[2][2] = fmaf(s2, df2.z, accS[2][2]);
                accS[3][0] = fmaf(s3, df3.x, accS[3][0]);
                accS[3][1] = fmaf(s3, df3.y, accS[3][1]);
                accS[3][2] = fmaf(s3, df3.z, accS[3][2]);
            }
        }
    }

    const int i0 = i0b + w*TI;
    float* outp = isQ ? g_bqp : g_bkp;
    #pragma unroll
    for (int t = 0; t < TI; t++)
        #pragma unroll
        for (int b = 0; b < 3; b++)
            outp[(js*NN + (i0+t))*48 + c*3 + b] = accP[t][b];
    if (!isQ) {
        #pragma unroll
        for (int t = 0; t < TI; t++)
            #pragma unroll
            for (int b = 0; b < 3; b++)
                g_Sp[(js*NN + (i0+t))*48 + c*3 + b] = accS[t][b];  // c == r
    }
}

// ---------------------------------------------------------------------------
// Phase B: coalesced merge of partials, att outer, MLP1 -> g_lr; merge S.
// ---------------------------------------------------------------------------
__global__ __launch_bounds__(256) void phaseB(const float* __restrict__ W1,
                                              const float* __restrict__ b1,
                                              const float* __restrict__ W2)
{
    const int i = blockIdx.x;
    const int tid = threadIdx.x;
    __shared__ __align__(16) float s_m[3][JS][64];
    __shared__ float s_bk[48], s_bq[48], s_att[256], s_y[16];

    #pragma unroll
    for (int k = 0; k < 3; k++) {
        int idx = tid + k*256;
        if (idx < 3*JS*12) {
            int v = idx / (JS*12), rem = idx % (JS*12);
            int js = rem / 12, f = rem % 12;
            const float4* src = (v == 0) ? (const float4*)g_bkp
                              : (v == 1) ? (const float4*)g_bqp
                                         : (const float4*)g_Sp;
            *(float4*)&s_m[v][js][f*4] = src[(js*NN + i)*12 + f];
        }
    }
    __syncthreads();

    if (tid < 144) {
        int v = tid / 48, e = tid % 48;
        float s = 0.f;
        #pragma unroll
        for (int js = 0; js < JS; js++) s += s_m[v][js][e];
        if (v == 0) s_bk[e] = s;
        else if (v == 1) s_bq[e] = s;
        else g_S[i*48 + e] = s;
    }
    __syncthreads();

    {
        int h = tid >> 4, g = tid & 15;
        s_att[tid] = s_bk[h*3+0]*s_bq[g*3+0] + s_bk[h*3+1]*s_bq[g*3+1]
                   + s_bk[h*3+2]*s_bq[g*3+2];
    }
    __syncthreads();

    {
        int h = tid >> 4, t = tid & 15;
        const float* w = W1 + h*256 + t;
        float p = 0.f;
        #pragma unroll
        for (int q = 0; q < 16; q++) p = fmaf(s_att[t + 16*q], w[16*q], p);
        #pragma unroll
        for (int m = 8; m >= 1; m >>= 1) p += __shfl_xor_sync(0xffffffffu, p, m, 16);
        if (t == 0) {
            float y = p + b1[h];
            s_y[h] = y / (1.0f + __expf(-y));
        }
    }
    __syncthreads();

    #pragma unroll
    for (int q = 0; q < 4; q++) {
        int m = tid + 256*q;
        const float* w = W2 + m*16;
        float a = 0.f;
        #pragma unroll
        for (int o = 0; o < 16; o++) a = fmaf(s_y[o], w[o], a);
        g_lr[i*1024 + m] = a;
    }
}

// ---------------------------------------------------------------------------
// Phase C: second contraction (right-stream), pairs recomputed in place.
// ---------------------------------------------------------------------------
__global__ __launch_bounds__(BLK, 3) void phaseC(const float* __restrict__ x)
{
    __shared__ float s_xi[96], s_xj[96];
    __shared__ __align__(16) float s_R[JCH*544];          // 17.4KB (K|pad|Q rows)
    __shared__ __align__(16) float4 s_SM4[4][JCH][32];
    __shared__ __align__(16) float4 s_DF[JCH][32];

    const int tid  = threadIdx.x;
    const int w    = tid >> 5;
    const int lane = tid & 31;
    const int igb  = blockIdx.x >> 4;
    const int js   = blockIdx.x & (JS-1);
    const int i0b  = igb*32;
    const int c    = lane & 15;
    const bool isQ = lane >= 16;

    if (tid < 96)            s_xi[tid]    = x[i0b*3 + tid];
    else if (tid < 192)      s_xj[tid-96] = x[js*JPW*3 + (tid-96)];

    float accP[TI][3];
    #pragma unroll
    for (int t = 0; t < TI; t++)
        #pragma unroll
        for (int b = 0; b < 3; b++) accP[t][b] = 0.f;

    __syncthreads();

    for (int ch = 0; ch < NCH; ch++) {
        const int j0 = js*JPW + ch*JCH;
        if (ch) __syncthreads();
        {   // stage right half of lr: 8 j x 512 floats (padded rows of 544)
            float4* dst = (float4*)s_R;
            const float4* src = (const float4*)g_lr;
            #pragma unroll
            for (int f = 0; f < 4; f++) {
                int idx = tid + f*256;
                int jl = idx >> 7, o = idx & 127;
                dst[jl*136 + o + ((o >= 64) ? 4 : 0)] = src[(j0+jl)*256 + 128 + o];
            }
        }
        gen_pair(s_xi, s_xj, lane, ch*JCH + w, s_SM4, s_DF, w, lane);
        __syncthreads();

        #pragma unroll 4
        for (int jl = 0; jl < JCH; jl++) {
            const float* wp = &s_R[jl*544 + (isQ ? 272 : 0) + c];
            float P0=0.f, P1=0.f, P2=0.f, P3=0.f;
            #pragma unroll
            for (int rg = 0; rg < 4; rg++) {
                float w0 = wp[(rg*4+0)*16];
                float w1 = wp[(rg*4+1)*16];
                float w2 = wp[(rg*4+2)*16];
                float w3 = wp[(rg*4+3)*16];
                float4 a0 = s_SM4[rg][jl][w*TI+0];
                float4 a1 = s_SM4[rg][jl][w*TI+1];
                float4 a2 = s_SM4[rg][jl][w*TI+2];
                float4 a3 = s_SM4[rg][jl][w*TI+3];
                P0 = fmaf(a0.x,w0, fmaf(a0.y,w1, fmaf(a0.z,w2, fmaf(a0.w,w3, P0))));
                P1 = fmaf(a1.x,w0, fmaf(a1.y,w1, fmaf(a1.z,w2, fmaf(a1.w,w3, P1))));
                P2 = fmaf(a2.x,w0, fmaf(a2.y,w1, fmaf(a2.z,w2, fmaf(a2.w,w3, P2))));
                P3 = fmaf(a3.x,w0, fmaf(a3.y,w1, fmaf(a3.z,w2, fmaf(a3.w,w3, P3))));
            }

            float4 df0 = s_DF[jl][w*TI+0];
            float4 df1 = s_DF[jl][w*TI+1];
            float4 df2 = s_DF[jl][w*TI+2];
            float4 df3 = s_DF[jl][w*TI+3];

            accP[0][0] = fmaf(P0, df0.x, accP[0][0]);
            accP[0][1] = fmaf(P0, df0.y, accP[0][1]);
            accP[0][2] = fmaf(P0, df0.z, accP[0][2]);
            accP[1][0] = fmaf(P1, df1.x, accP[1][0]);
            accP[1][1] = fmaf(P1, df1.y, accP[1][1]);
            accP[1][2] = fmaf(P1, df1.z, accP[1][2]);
            accP[2][0] = fmaf(P2, df2.x, accP[2][0]);
            accP[2][1] = fmaf(P2, df2.y, accP[2][1]);
            accP[2][2] = fmaf(P2, df2.z, accP[2][2]);
            accP[3][0] = fmaf(P3, df3.x, accP[3][0]);
            accP[3][1] = fmaf(P3, df3.y, accP[3][1]);
            accP[3][2] = fmaf(P3, df3.z, accP[3][2]);
        }
    }

    const int i0 = i0b + w*TI;
    float* outp = isQ ? g_bq2p : g_bk2p;
    #pragma unroll
    for (int t = 0; t < TI; t++)
        #pragma unroll
        for (int b = 0; b < 3; b++)
            outp[(js*NN + (i0+t))*48 + c*3 + b] = accP[t][b];
}

// ---------------------------------------------------------------------------
// Phase D: coalesced merge + left⊗S term, att outer, MLP2, output.
// ---------------------------------------------------------------------------
__global__ __launch_bounds__(256) void phaseD(const float* __restrict__ W3,
                                              const float* __restrict__ b3,
                                              const float* __restrict__ W4,
                                              const float* __restrict__ b4,
                                              float* __restrict__ out)
{
    const int i = blockIdx.x;
    const int tid = threadIdx.x;
    __shared__ __align__(16) float s_m[2][JS][64];
    __shared__ float s_bk[48], s_bq[48], s_att[256], s_y[16];

    #pragma unroll
    for (int k = 0; k < 2; k++) {
        int idx = tid + k*256;
        if (idx < 2*JS*12) {
            int v = idx / (JS*12), rem = idx % (JS*12);
            int js = rem / 12, f = rem % 12;
            const float4* src = (v == 0) ? (const float4*)g_bk2p
                                         : (const float4*)g_bq2p;
            *(float4*)&s_m[v][js][f*4] = src[(js*NN + i)*12 + f];
        }
    }
    __syncthreads();

    if (tid < 96) {
        int v = tid / 48, e = tid % 48;
        int cc = e / 3, b = e % 3;
        float s = 0.f;
        #pragma unroll
        for (int js = 0; js < JS; js++) s += s_m[v][js][e];
        const float* lp = g_lr + i*1024 + (v ? 256 : 0) + cc;
        const float* sp = g_S  + i*48 + b;
        #pragma unroll
        for (int r = 0; r < 16; r++) s = fmaf(lp[r*16], sp[r*3], s);
        if (v == 0) s_bk[e] = s; else s_bq[e] = s;
    }
    __syncthreads();

    {
        int h = tid >> 4, g = tid & 15;
        s_att[tid] = s_bk[h*3+0]*s_bq[g*3+0] + s_bk[h*3+1]*s_bq[g*3+1]
                   + s_bk[h*3+2]*s_bq[g*3+2];
    }
    __syncthreads();

    {
        int h = tid >> 4, t = tid & 15;
        const float* w = W3 + h*256 + t;
        float p = 0.f;
        #pragma unroll
        for (int q = 0; q < 16; q++) p = fmaf(s_att[t + 16*q], w[16*q], p);
        #pragma unroll
        for (int m = 8; m >= 1; m >>= 1) p += __shfl_xor_sync(0xffffffffu, p, m, 16);
        if (t == 0) {
            float y = p + b3[h];
            s_y[h] = y / (1.0f + __expf(-y));
        }
    }
    __syncthreads();

    if (tid == 0) {
        float a = b4[0];
        #pragma unroll
        for (int o = 0; o < 16; o++) a = fmaf(s_y[o], W4[o], a);
        out[i] = a;
    }
}

// ---------------------------------------------------------------------------
extern "C" void kernel_launch(void* const* d_in, const int* in_sizes, int n_in,
                              void* d_out, int out_size)
{
    const float* x  = (const float*)d_in[0];
    const float* W  = (const float*)d_in[1];
    const float* W1 = (const float*)d_in[2];
    const float* b1 = (const float*)d_in[3];
    const float* W2 = (const float*)d_in[4];
    const float* W3 = (const float*)d_in[5];
    const float* b3 = (const float*)d_in[6];
    const float* W4 = (const float*)d_in[7];
    const float* b4 = (const float*)d_in[8];
    float* out = (float*)d_out;

    phaseA<<<GRID_AC, BLK>>>(x, W);
    phaseB<<<NN, 256>>>(W1, b1, W2);
    phaseC<<<GRID_AC, BLK>>>(x);
    phaseD<<<NN, 256>>>(W3, b3, W4, b4, out);
}

// round 13
// speedup vs baseline: 1.4235x; 1.1242x over previous
#include <cuda_runtime.h>

#define NN 512
#define RR 16
#define HH 16
#define TI 4               // i-rows per warp (contraction)
#define JS 16              // j slices (partial buffers)
#define JPW (NN/JS)        // 32 j per slice
#define JCH 8              // j's per chunk
#define NCH (JPW/JCH)      // 4 chunks
#define BLK 256
#define GRID_AC ((NN/32)*JS)     // 256 blocks
#define IB 4                     // i's per block in B/D

// smearing constants (f32)
#define SM_START 0.006737946999085467f
#define SM_MSTEP ((1.0f - SM_START) * (1.0f/15.0f))
#define SM_SBETA (0.125f * (1.0f - SM_START))
#define SM_BETA  (1.0f / (SM_SBETA * SM_SBETA))
#define PI_OVER5 0.6283185307179586f

// scratch (small only — no pair tensors)
__device__ float g_bkp [JS*NN*48];
__device__ float g_bqp [JS*NN*48];
__device__ float g_Sp  [JS*NN*48];
__device__ float g_S   [NN*48];
__device__ float g_lr  [NN*1024];                // left(512)|right(512)
__device__ float g_bk2p[JS*NN*48];
__device__ float g_bq2p[JS*NN*48];

// ---------------------------------------------------------------------------
// In-place pair generation: thread (il=lane, j=chunk j0+w) computes one pair:
// diffn float4 + 16 smearing values -> s_SMS[w][lane][r] (stride 20) + s_DF.
// ---------------------------------------------------------------------------
__device__ __forceinline__ void gen_pair(const float* s_xi, const float* s_xj,
                                         int il, int jsl,
                                         float* s_SMS, float4 (*s_DF)[32],
                                         int w, int lane)
{
    const float dx = s_xi[il*3+0] - s_xj[jsl*3+0];
    const float dy = s_xi[il*3+1] - s_xj[jsl*3+1];
    const float dz = s_xi[il*3+2] - s_xj[jsl*3+2];
    const float nsq = fmaf(dx,dx, fmaf(dy,dy, fmaf(dz,dz, 1e-6f)));
    const float rin = rsqrtf(nsq);
    const float d   = nsq * rin;
    const float inv = rin * rin;
    s_DF[w][lane] = make_float4(dx*inv, dy*inv, dz*inv, 0.f);

    const float e   = __expf(-d);
    const float cut = (d < 5.0f) ? 0.5f*(__cosf(d*PI_OVER5) + 1.0f) : 0.0f;
    float* dst = s_SMS + (w*32 + lane)*20;
    #pragma unroll
    for (int rg = 0; rg < 4; rg++) {
        float u0 = e - (SM_START + SM_MSTEP*(float)(rg*4+0));
        float u1 = e - (SM_START + SM_MSTEP*(float)(rg*4+1));
        float u2 = e - (SM_START + SM_MSTEP*(float)(rg*4+2));
        float u3 = e - (SM_START + SM_MSTEP*(float)(rg*4+3));
        float4 v;
        v.x = cut * __expf(-SM_BETA*u0*u0);
        v.y = cut * __expf(-SM_BETA*u1*u1);
        v.z = cut * __expf(-SM_BETA*u2*u2);
        v.w = cut * __expf(-SM_BETA*u3*u3);
        *(float4*)(dst + rg*4) = v;
    }
}

// ---------------------------------------------------------------------------
// Phase A: first contraction. Transposed weights [half][jl][c][20], sm in
// s_SMS [jl][il][20]. Lanes 0-15 K (c=lane), 16-31 Q.
// ---------------------------------------------------------------------------
__global__ __launch_bounds__(BLK, 3) void phaseA(const float* __restrict__ x,
                                                 const float* __restrict__ W)
{
    __shared__ float s_xi[96], s_xj[96];
    __shared__ __align__(16) float s_WT[2*JCH*16*20];     // 20KB
    __shared__ __align__(16) float s_SMS[JCH*32*20];      // 20KB
    __shared__ __align__(16) float4 s_DF[JCH][32];        // 4KB

    const int tid  = threadIdx.x;
    const int w    = tid >> 5;
    const int lane = tid & 31;
    const int igb  = blockIdx.x >> 4;
    const int js   = blockIdx.x & (JS-1);
    const int i0b  = igb*32;
    const int c    = lane & 15;
    const bool isQ = lane >= 16;

    if (tid < 96)            s_xi[tid]    = x[i0b*3 + tid];
    else if (tid < 192)      s_xj[tid-96] = x[js*JPW*3 + (tid-96)];

    float accP[TI][3], accS[TI][3];
    #pragma unroll
    for (int t = 0; t < TI; t++)
        #pragma unroll
        for (int b = 0; b < 3; b++) { accP[t][b] = 0.f; accS[t][b] = 0.f; }

    __syncthreads();

    for (int ch = 0; ch < NCH; ch++) {
        const int j0 = js*JPW + ch*JCH;
        if (ch) __syncthreads();
        {   // stage weights transposed: [jl][c][r] stride 20
            const float4* srcK = (const float4*)(W + j0*256);
            const float4* srcQ = (const float4*)(W + NN*RR*HH + j0*256);
            #pragma unroll
            for (int k = 0; k < 2; k++) {
                int idx = tid + k*256;            // 0..511
                int jl = idx >> 6, rem = idx & 63;
                int r = rem >> 2, c4 = (rem & 3) << 2;
                float* dk = &s_WT[(jl*16 + c4)*20 + r];
                float4 vk = srcK[idx];
                dk[0] = vk.x; dk[20] = vk.y; dk[40] = vk.z; dk[60] = vk.w;
                float* dq = &s_WT[2560 + (jl*16 + c4)*20 + r];
                float4 vq = srcQ[idx];
                dq[0] = vq.x; dq[20] = vq.y; dq[40] = vq.z; dq[60] = vq.w;
            }
        }
        gen_pair(s_xi, s_xj, lane, ch*JCH + w, s_SMS, s_DF, w, lane);
        __syncthreads();

        #pragma unroll 2
        for (int jl = 0; jl < JCH; jl++) {
            const float* wp = &s_WT[(isQ ? 2560 : 0) + (jl*16 + c)*20];
            float4 w0 = *(const float4*)(wp);
            float4 w1 = *(const float4*)(wp+4);
            float4 w2 = *(const float4*)(wp+8);
            float4 w3 = *(const float4*)(wp+12);
            const float* smb = &s_SMS[(jl*32 + (w<<2))*20];

            float P[TI];
            #pragma unroll
            for (int t = 0; t < TI; t++) {
                const float* sr = smb + t*20;
                float4 a0 = *(const float4*)(sr);
                float4 a1 = *(const float4*)(sr+4);
                float4 a2 = *(const float4*)(sr+8);
                float4 a3 = *(const float4*)(sr+12);
                float p;
                p = a0.x*w0.x;        p = fmaf(a0.y,w0.y,p);
                p = fmaf(a0.z,w0.z,p); p = fmaf(a0.w,w0.w,p);
                p = fmaf(a1.x,w1.x,p); p = fmaf(a1.y,w1.y,p);
                p = fmaf(a1.z,w1.z,p); p = fmaf(a1.w,w1.w,p);
                p = fmaf(a2.x,w2.x,p); p = fmaf(a2.y,w2.y,p);
                p = fmaf(a2.z,w2.z,p); p = fmaf(a2.w,w2.w,p);
                p = fmaf(a3.x,w3.x,p); p = fmaf(a3.y,w3.y,p);
                p = fmaf(a3.z,w3.z,p); p = fmaf(a3.w,w3.w,p);
                P[t] = p;
            }

            #pragma unroll
            for (int t = 0; t < TI; t++) {
                float4 df = s_DF[jl][(w<<2)+t];
                accP[t][0] = fmaf(P[t], df.x, accP[t][0]);
                accP[t][1] = fmaf(P[t], df.y, accP[t][1]);
                accP[t][2] = fmaf(P[t], df.z, accP[t][2]);
                if (!isQ) {   // S-term: lane c plays r=c, conflict-free
                    float sv = s_SMS[(jl*32 + (w<<2)+t)*20 + c];
                    accS[t][0] = fmaf(sv, df.x, accS[t][0]);
                    accS[t][1] = fmaf(sv, df.y, accS[t][1]);
                    accS[t][2] = fmaf(sv, df.z, accS[t][2]);
                }
            }
        }
    }

    const int i0 = i0b + w*TI;
    float* outp = isQ ? g_bqp : g_bkp;
    #pragma unroll
    for (int t = 0; t < TI; t++)
        #pragma unroll
        for (int b = 0; b < 3; b++)
            outp[(js*NN + (i0+t))*48 + c*3 + b] = accP[t][b];
    if (!isQ) {
        #pragma unroll
        for (int t = 0; t < TI; t++)
            #pragma unroll
            for (int b = 0; b < 3; b++)
                g_Sp[(js*NN + (i0+t))*48 + c*3 + b] = accS[t][b];  // c == r
    }
}

// ---------------------------------------------------------------------------
// Phase B: 4 i per block; W1 staged; partials merged in 3 coalesced passes.
// ---------------------------------------------------------------------------
__global__ __launch_bounds__(256) void phaseB(const float* __restrict__ W1,
                                              const float* __restrict__ b1,
                                              const float* __restrict__ W2)
{
    const int i0  = blockIdx.x * IB;
    const int tid = threadIdx.x;
    __shared__ __align__(16) float s_W1[4096];            // 16KB
    __shared__ __align__(16) float s_buf[JS][IB][48];     // 12KB
    __shared__ float s_bk[IB][48], s_bq[IB][48];
    __shared__ float s_att[256];
    __shared__ float s_y[IB][16];

    {
        float4* d = (float4*)s_W1;
        const float4* s = (const float4*)W1;
        #pragma unroll
        for (int k = 0; k < 4; k++) d[tid + k*256] = s[tid + k*256];
    }

    #pragma unroll
    for (int v = 0; v < 3; v++) {
        __syncthreads();
        const float4* src = (v == 0) ? (const float4*)g_bkp
                          : (v == 1) ? (const float4*)g_bqp
                                     : (const float4*)g_Sp;
        #pragma unroll
        for (int k = 0; k < 3; k++) {
            int idx = tid + k*256;           // 768 = 16js*4ib*12f
            int js = idx/48, rem = idx%48, ib = rem/12, f = rem%12;
            *(float4*)&s_buf[js][ib][f*4] = src[(js*NN + i0+ib)*12 + f];
        }
        __syncthreads();
        if (tid < 192) {
            int ib = tid/48, e = tid%48;
            float s = 0.f;
            #pragma unroll
            for (int js = 0; js < JS; js++) s += s_buf[js][ib][e];
            if (v == 0) s_bk[ib][e] = s;
            else if (v == 1) s_bq[ib][e] = s;
            else g_S[(i0+ib)*48 + e] = s;
        }
    }
    __syncthreads();

    for (int ib = 0; ib < IB; ib++) {
        int h = tid >> 4, g = tid & 15;
        s_att[tid] = s_bk[ib][h*3+0]*s_bq[ib][g*3+0]
                   + s_bk[ib][h*3+1]*s_bq[ib][g*3+1]
                   + s_bk[ib][h*3+2]*s_bq[ib][g*3+2];
        __syncthreads();
        {
            int t = tid & 15;
            const float* wr = &s_W1[h*256 + t];
            float p = 0.f;
            #pragma unroll
            for (int q = 0; q < 16; q++) p = fmaf(s_att[t + 16*q], wr[16*q], p);
            #pragma unroll
            for (int m = 8; m >= 1; m >>= 1) p += __shfl_xor_sync(0xffffffffu, p, m, 16);
            if (t == 0) {
                float y = p + b1[h];
                s_y[ib][h] = y / (1.0f + __expf(-y));
            }
        }
        __syncthreads();
    }

    // out: each thread owns 4 m's, reuses the W2 row across the 4 i's
    #pragma unroll
    for (int k = 0; k < 4; k++) {
        int m = tid + k*256;
        const float4* wr = (const float4*)(W2 + m*16);
        float4 q0 = __ldg(wr), q1 = __ldg(wr+1), q2 = __ldg(wr+2), q3 = __ldg(wr+3);
        #pragma unroll
        for (int ib = 0; ib < IB; ib++) {
            const float* y = s_y[ib];
            float a;
            a = q0.x*y[0];         a = fmaf(q0.y,y[1],a);
            a = fmaf(q0.z,y[2],a); a = fmaf(q0.w,y[3],a);
            a = fmaf(q1.x,y[4],a); a = fmaf(q1.y,y[5],a);
            a = fmaf(q1.z,y[6],a); a = fmaf(q1.w,y[7],a);
            a = fmaf(q2.x,y[8],a); a = fmaf(q2.y,y[9],a);
            a = fmaf(q2.z,y[10],a); a = fmaf(q2.w,y[11],a);
            a = fmaf(q3.x,y[12],a); a = fmaf(q3.y,y[13],a);
            a = fmaf(q3.z,y[14],a); a = fmaf(q3.w,y[15],a);
            g_lr[(i0+ib)*1024 + m] = a;
        }
    }
}

// ---------------------------------------------------------------------------
// Phase C: second contraction (right-stream). Transposed lr [half][jl][c][20].
// ---------------------------------------------------------------------------
__global__ __launch_bounds__(BLK, 3) void phaseC(const float* __restrict__ x)
{
    __shared__ float s_xi[96], s_xj[96];
    __shared__ __align__(16) float s_RT[2*JCH*16*20];     // 20KB
    __shared__ __align__(16) float s_SMS[JCH*32*20];      // 20KB
    __shared__ __align__(16) float4 s_DF[JCH][32];

    const int tid  = threadIdx.x;
    const int w    = tid >> 5;
    const int lane = tid & 31;
    const int igb  = blockIdx.x >> 4;
    const int js   = blockIdx.x & (JS-1);
    const int i0b  = igb*32;
    const int c    = lane & 15;
    const bool isQ = lane >= 16;

    if (tid < 96)            s_xi[tid]    = x[i0b*3 + tid];
    else if (tid < 192)      s_xj[tid-96] = x[js*JPW*3 + (tid-96)];

    float accP[TI][3];
    #pragma unroll
    for (int t = 0; t < TI; t++)
        #pragma unroll
        for (int b = 0; b < 3; b++) accP[t][b] = 0.f;

    __syncthreads();

    for (int ch = 0; ch < NCH; ch++) {
        const int j0 = js*JPW + ch*JCH;
        if (ch) __syncthreads();
        {   // stage right half of lr transposed
            const float4* src = (const float4*)g_lr;
            #pragma unroll
            for (int k = 0; k < 4; k++) {
                int idx = tid + k*256;          // 0..1023 = 8j * 128
                int jl = idx >> 7, n = idx & 127;
                int half = n >> 6, rem2 = n & 63;
                int r = rem2 >> 2, c4 = (rem2 & 3) << 2;
                float4 v = src[(j0+jl)*256 + 128 + n];
                float* d = &s_RT[((half*JCH + jl)*16 + c4)*20 + r];
                d[0] = v.x; d[20] = v.y; d[40] = v.z; d[60] = v.w;
            }
        }
        gen_pair(s_xi, s_xj, lane, ch*JCH + w, s_SMS, s_DF, w, lane);
        __syncthreads();

        #pragma unroll 4
        for (int jl = 0; jl < JCH; jl++) {
            const float* wp = &s_RT[(isQ ? 2560 : 0) + (jl*16 + c)*20];
            float4 w0 = *(const float4*)(wp);
            float4 w1 = *(const float4*)(wp+4);
            float4 w2 = *(const float4*)(wp+8);
            float4 w3 = *(const float4*)(wp+12);
            const float* smb = &s_SMS[(jl*32 + (w<<2))*20];

            float P[TI];
            #pragma unroll
            for (int t = 0; t < TI; t++) {
                const float* sr = smb + t*20;
                float4 a0 = *(const float4*)(sr);
                float4 a1 = *(const float4*)(sr+4);
                float4 a2 = *(const float4*)(sr+8);
                float4 a3 = *(const float4*)(sr+12);
                float p;
                p = a0.x*w0.x;        p = fmaf(a0.y,w0.y,p);
                p = fmaf(a0.z,w0.z,p); p = fmaf(a0.w,w0.w,p);
                p = fmaf(a1.x,w1.x,p); p = fmaf(a1.y,w1.y,p);
                p = fmaf(a1.z,w1.z,p); p = fmaf(a1.w,w1.w,p);
                p = fmaf(a2.x,w2.x,p); p = fmaf(a2.y,w2.y,p);
                p = fmaf(a2.z,w2.z,p); p = fmaf(a2.w,w2.w,p);
                p = fmaf(a3.x,w3.x,p); p = fmaf(a3.y,w3.y,p);
                p = fmaf(a3.z,w3.z,p); p = fmaf(a3.w,w3.w,p);
                P[t] = p;
            }

            #pragma unroll
            for (int t = 0; t < TI; t++) {
                float4 df = s_DF[jl][(w<<2)+t];
                accP[t][0] = fmaf(P[t], df.x, accP[t][0]);
                accP[t][1] = fmaf(P[t], df.y, accP[t][1]);
                accP[t][2] = fmaf(P[t], df.z, accP[t][2]);
            }
        }
    }

    const int i0 = i0b + w*TI;
    float* outp = isQ ? g_bq2p : g_bk2p;
    #pragma unroll
    for (int t = 0; t < TI; t++)
        #pragma unroll
        for (int b = 0; b < 3; b++)
            outp[(js*NN + (i0+t))*48 + c*3 + b] = accP[t][b];
}

// ---------------------------------------------------------------------------
// Phase D: 4 i per block; W3 staged; merge + left⊗S; MLP2; output.
// ---------------------------------------------------------------------------
__global__ __launch_bounds__(256) void phaseD(const float* __restrict__ W3,
                                              const float* __restrict__ b3,
                                              const float* __restrict__ W4,
                                              const float* __restrict__ b4,
                                              float* __restrict__ out)
{
    const int i0  = blockIdx.x * IB;
    const int tid = threadIdx.x;
    __shared__ __align__(16) float s_W3[4096];            // 16KB
    __shared__ __align__(16) float s_buf[JS][IB][48];     // 12KB
    __shared__ __align__(16) float s_L[IB][512];          // 8KB (left halves)
    __shared__ float s_S[IB][48];
    __shared__ float s_bk[IB][48], s_bq[IB][48];
    __shared__ float s_att[256];
    __shared__ float s_y[IB][16];

    {
        float4* d = (float4*)s_W3;
        const float4* s = (const float4*)W3;
        #pragma unroll
        for (int k = 0; k < 4; k++) d[tid + k*256] = s[tid + k*256];
    }
    {   // stage left halves of lr for the 4 i's
        float4* d = (float4*)s_L;
        const float4* s = (const float4*)g_lr;
        #pragma unroll
        for (int k = 0; k < 2; k++) {
            int idx = tid + k*256;           // 512 = 4ib*128
            int ib = idx >> 7, o = idx & 127;
            d[ib*128 + o] = s[(i0+ib)*256 + o];
        }
    }
    if (tid < IB*48) ((float*)s_S)[tid] = g_S[i0*48 + tid];

    #pragma unroll
    for (int v = 0; v < 2; v++) {
        __syncthreads();
        const float4* src = (v == 0) ? (const float4*)g_bk2p
                                     : (const float4*)g_bq2p;
        #pragma unroll
        for (int k = 0; k < 3; k++) {
            int idx = tid + k*256;
            int js = idx/48, rem = idx%48, ib = rem/12, f = rem%12;
            *(float4*)&s_buf[js][ib][f*4] = src[(js*NN + i0+ib)*12 + f];
        }
        __syncthreads();
        if (tid < 192) {
            int ib = tid/48, e = tid%48;
            int cc = e/3, b = e%3;
            float s = 0.f;
            #pragma unroll
            for (int js = 0; js < JS; js++) s += s_buf[js][ib][e];
            const float* lp = &s_L[ib][(v ? 256 : 0) + cc];
            #pragma unroll
            for (int r = 0; r < 16; r++) s = fmaf(lp[r*16], s_S[ib][r*3+b], s);
            if (v == 0) s_bk[ib][e] = s; else s_bq[ib][e] = s;
        }
    }
    __syncthreads();

    for (int ib = 0; ib < IB; ib++) {
        int h = tid >> 4, g = tid & 15;
        s_att[tid] = s_bk[ib][h*3+0]*s_bq[ib][g*3+0]
                   + s_bk[ib][h*3+1]*s_bq[ib][g*3+1]
                   + s_bk[ib][h*3+2]*s_bq[ib][g*3+2];
        __syncthreads();
        {
            int t = tid & 15;
            const float* wr = &s_W3[h*256 + t];
            float p = 0.f;
            #pragma unroll
            for (int q = 0; q < 16; q++) p = fmaf(s_att[t + 16*q], wr[16*q], p);
            #pragma unroll
            for (int m = 8; m >= 1; m >>= 1) p += __shfl_xor_sync(0xffffffffu, p, m, 16);
            if (t == 0) {
                float y = p + b3[h];
                s_y[ib][h] = y / (1.0f + __expf(-y));
            }
        }
        __syncthreads();
        if (tid == 0) {
            float a = b4[0];
            #pragma unroll
            for (int o = 0; o < 16; o++) a = fmaf(s_y[ib][o], W4[o], a);
            out[i0+ib] = a;
        }
    }
}

// ---------------------------------------------------------------------------
extern "C" void kernel_launch(void* const* d_in, const int* in_sizes, int n_in,
                              void* d_out, int out_size)
{
    const float* x  = (const float*)d_in[0];
    const float* W  = (const float*)d_in[1];
    const float* W1 = (const float*)d_in[2];
    const float* b1 = (const float*)d_in[3];
    const float* W2 = (const float*)d_in[4];
    const float* W3 = (const float*)d_in[5];
    const float* b3 = (const float*)d_in[6];
    const float* W4 = (const float*)d_in[7];
    const float* b4 = (const float*)d_in[8];
    float* out = (float*)d_out;

    phaseA<<<GRID_AC, BLK>>>(x, W);
    phaseB<<<NN/IB, 256>>>(W1, b1, W2);
    phaseC<<<GRID_AC, BLK>>>(x);
    phaseD<<<NN/IB, 256>>>(W3, b3, W4, b4, out);
}

// round 14
// speedup vs baseline: 1.5080x; 1.0594x over previous
#include <cuda_runtime.h>

#define NN 512
#define RR 16
#define HH 16
#define TI 4               // i-rows per warp (contraction)
#define JS 32              // j slices (partial buffers)
#define JPW (NN/JS)        // 16 j per slice
#define JCH 8              // j's per chunk
#define NCH (JPW/JCH)      // 2 chunks
#define BLK 256
#define GRID_AC ((NN/32)*JS)     // 16 * 32 = 512 blocks

// smearing constants (f32)
#define SM_START 0.006737946999085467f
#define SM_MSTEP ((1.0f - SM_START) * (1.0f/15.0f))
#define SM_SBETA (0.125f * (1.0f - SM_START))
#define SM_BETA  (1.0f / (SM_SBETA * SM_SBETA))
#define PI_OVER5 0.6283185307179586f

// scratch (small only — no pair tensors)
__device__ float g_bkp [JS*NN*48];
__device__ float g_bqp [JS*NN*48];
__device__ float g_Sp  [JS*NN*48];
__device__ float g_S   [NN*48];
__device__ float g_lr  [NN*1024];                // left(512)|right(512)
__device__ float g_bk2p[JS*NN*48];
__device__ float g_bq2p[JS*NN*48];

// ---------------------------------------------------------------------------
// In-place pair generation: thread (il=lane, j=chunk j0+w) computes one pair:
// diffn float4 + 16 smearing values -> s_SMS[w][lane][r] (stride 20) + s_DF.
// ---------------------------------------------------------------------------
__device__ __forceinline__ void gen_pair(const float* s_xi, const float* s_xj,
                                         int il, int jsl,
                                         float* s_SMS, float4 (*s_DF)[32],
                                         int w, int lane)
{
    const float dx = s_xi[il*3+0] - s_xj[jsl*3+0];
    const float dy = s_xi[il*3+1] - s_xj[jsl*3+1];
    const float dz = s_xi[il*3+2] - s_xj[jsl*3+2];
    const float nsq = fmaf(dx,dx, fmaf(dy,dy, fmaf(dz,dz, 1e-6f)));
    const float rin = rsqrtf(nsq);
    const float d   = nsq * rin;
    const float inv = rin * rin;
    s_DF[w][lane] = make_float4(dx*inv, dy*inv, dz*inv, 0.f);

    const float e   = __expf(-d);
    const float cut = (d < 5.0f) ? 0.5f*(__cosf(d*PI_OVER5) + 1.0f) : 0.0f;
    float* dst = s_SMS + (w*32 + lane)*20;
    #pragma unroll
    for (int rg = 0; rg < 4; rg++) {
        float u0 = e - (SM_START + SM_MSTEP*(float)(rg*4+0));
        float u1 = e - (SM_START + SM_MSTEP*(float)(rg*4+1));
        float u2 = e - (SM_START + SM_MSTEP*(float)(rg*4+2));
        float u3 = e - (SM_START + SM_MSTEP*(float)(rg*4+3));
        float4 v;
        v.x = cut * __expf(-SM_BETA*u0*u0);
        v.y = cut * __expf(-SM_BETA*u1*u1);
        v.z = cut * __expf(-SM_BETA*u2*u2);
        v.w = cut * __expf(-SM_BETA*u3*u3);
        *(float4*)(dst + rg*4) = v;
    }
}

// ---------------------------------------------------------------------------
// Phase A: first contraction. Transposed weights [half][jl][c][20], sm in
// s_SMS [jl][il][20]. Lanes 0-15 K (c=lane), 16-31 Q.
// ---------------------------------------------------------------------------
__global__ __launch_bounds__(BLK, 3) void phaseA(const float* __restrict__ x,
                                                 const float* __restrict__ W)
{
    __shared__ float s_xi[96], s_xj[48];
    __shared__ __align__(16) float s_WT[2*JCH*16*20];     // 20KB
    __shared__ __align__(16) float s_SMS[JCH*32*20];      // 20KB
    __shared__ __align__(16) float4 s_DF[JCH][32];        // 4KB

    const int tid  = threadIdx.x;
    const int w    = tid >> 5;
    const int lane = tid & 31;
    const int igb  = blockIdx.x >> 5;        // / JS
    const int js   = blockIdx.x & (JS-1);
    const int i0b  = igb*32;
    const int c    = lane & 15;
    const bool isQ = lane >= 16;

    if (tid < 96)            s_xi[tid]    = x[i0b*3 + tid];
    else if (tid < 144)      s_xj[tid-96] = x[js*JPW*3 + (tid-96)];

    float accP[TI][3], accS[TI][3];
    #pragma unroll
    for (int t = 0; t < TI; t++)
        #pragma unroll
        for (int b = 0; b < 3; b++) { accP[t][b] = 0.f; accS[t][b] = 0.f; }

    __syncthreads();

    for (int ch = 0; ch < NCH; ch++) {
        const int j0 = js*JPW + ch*JCH;
        if (ch) __syncthreads();
        {   // stage weights transposed: [jl][c][r] stride 20
            const float4* srcK = (const float4*)(W + j0*256);
            const float4* srcQ = (const float4*)(W + NN*RR*HH + j0*256);
            #pragma unroll
            for (int k = 0; k < 2; k++) {
                int idx = tid + k*256;            // 0..511
                int jl = idx >> 6, rem = idx & 63;
                int r = rem >> 2, c4 = (rem & 3) << 2;
                float* dk = &s_WT[(jl*16 + c4)*20 + r];
                float4 vk = srcK[idx];
                dk[0] = vk.x; dk[20] = vk.y; dk[40] = vk.z; dk[60] = vk.w;
                float* dq = &s_WT[2560 + (jl*16 + c4)*20 + r];
                float4 vq = srcQ[idx];
                dq[0] = vq.x; dq[20] = vq.y; dq[40] = vq.z; dq[60] = vq.w;
            }
        }
        gen_pair(s_xi, s_xj, lane, ch*JCH + w, s_SMS, s_DF, w, lane);
        __syncthreads();

        #pragma unroll 2
        for (int jl = 0; jl < JCH; jl++) {
            const float* wp = &s_WT[(isQ ? 2560 : 0) + (jl*16 + c)*20];
            float4 w0 = *(const float4*)(wp);
            float4 w1 = *(const float4*)(wp+4);
            float4 w2 = *(const float4*)(wp+8);
            float4 w3 = *(const float4*)(wp+12);
            const float* smb = &s_SMS[(jl*32 + (w<<2))*20];

            float P[TI];
            #pragma unroll
            for (int t = 0; t < TI; t++) {
                const float* sr = smb + t*20;
                float4 a0 = *(const float4*)(sr);
                float4 a1 = *(const float4*)(sr+4);
                float4 a2 = *(const float4*)(sr+8);
                float4 a3 = *(const float4*)(sr+12);
                float p;
                p = a0.x*w0.x;        p = fmaf(a0.y,w0.y,p);
                p = fmaf(a0.z,w0.z,p); p = fmaf(a0.w,w0.w,p);
                p = fmaf(a1.x,w1.x,p); p = fmaf(a1.y,w1.y,p);
                p = fmaf(a1.z,w1.z,p); p = fmaf(a1.w,w1.w,p);
                p = fmaf(a2.x,w2.x,p); p = fmaf(a2.y,w2.y,p);
                p = fmaf(a2.z,w2.z,p); p = fmaf(a2.w,w2.w,p);
                p = fmaf(a3.x,w3.x,p); p = fmaf(a3.y,w3.y,p);
                p = fmaf(a3.z,w3.z,p); p = fmaf(a3.w,w3.w,p);
                P[t] = p;
            }

            #pragma unroll
            for (int t = 0; t < TI; t++) {
                float4 df = s_DF[jl][(w<<2)+t];
                accP[t][0] = fmaf(P[t], df.x, accP[t][0]);
                accP[t][1] = fmaf(P[t], df.y, accP[t][1]);
                accP[t][2] = fmaf(P[t], df.z, accP[t][2]);
                if (!isQ) {   // S-term: lane c plays r=c, conflict-free
                    float sv = s_SMS[(jl*32 + (w<<2)+t)*20 + c];
                    accS[t][0] = fmaf(sv, df.x, accS[t][0]);
                    accS[t][1] = fmaf(sv, df.y, accS[t][1]);
                    accS[t][2] = fmaf(sv, df.z, accS[t][2]);
                }
            }
        }
    }

    const int i0 = i0b + w*TI;
    float* outp = isQ ? g_bqp : g_bkp;
    #pragma unroll
    for (int t = 0; t < TI; t++)
        #pragma unroll
        for (int b = 0; b < 3; b++)
            outp[(js*NN + (i0+t))*48 + c*3 + b] = accP[t][b];
    if (!isQ) {
        #pragma unroll
        for (int t = 0; t < TI; t++)
            #pragma unroll
            for (int b = 0; b < 3; b++)
                g_Sp[(js*NN + (i0+t))*48 + c*3 + b] = accS[t][b];  // c == r
    }
}

// ---------------------------------------------------------------------------
// Phase B: one i per block (grid 512). Coalesced staged merge of 32 partials,
// att outer, MLP1 -> g_lr; merge S.
// ---------------------------------------------------------------------------
__global__ __launch_bounds__(256) void phaseB(const float* __restrict__ W1,
                                              const float* __restrict__ b1,
                                              const float* __restrict__ W2)
{
    const int i = blockIdx.x;
    const int tid = threadIdx.x;
    __shared__ __align__(16) float s_m[3][JS][48];        // 18KB
    __shared__ float s_bk[48], s_bq[48], s_att[256], s_y[16];

    #pragma unroll
    for (int k = 0; k < 5; k++) {
        int idx = tid + k*256;               // 1152 = 3*32*12
        if (idx < 3*JS*12) {
            int v = idx / (JS*12), rem = idx % (JS*12);
            int js = rem / 12, f = rem % 12;
            const float4* src = (v == 0) ? (const float4*)g_bkp
                              : (v == 1) ? (const float4*)g_bqp
                                         : (const float4*)g_Sp;
            *(float4*)&s_m[v][js][f*4] = src[(js*NN + i)*12 + f];
        }
    }
    __syncthreads();

    if (tid < 144) {
        int v = tid / 48, e = tid % 48;
        float s = 0.f;
        #pragma unroll
        for (int js = 0; js < JS; js++) s += s_m[v][js][e];
        if (v == 0) s_bk[e] = s;
        else if (v == 1) s_bq[e] = s;
        else g_S[i*48 + e] = s;
    }
    __syncthreads();

    {
        int h = tid >> 4, g = tid & 15;
        s_att[tid] = s_bk[h*3+0]*s_bq[g*3+0] + s_bk[h*3+1]*s_bq[g*3+1]
                   + s_bk[h*3+2]*s_bq[g*3+2];
    }
    __syncthreads();

    {
        int h = tid >> 4, t = tid & 15;
        const float* w = W1 + h*256 + t;
        float p = 0.f;
        #pragma unroll
        for (int q = 0; q < 16; q++) p = fmaf(s_att[t + 16*q], __ldg(&w[16*q]), p);
        #pragma unroll
        for (int m = 8; m >= 1; m >>= 1) p += __shfl_xor_sync(0xffffffffu, p, m, 16);
        if (t == 0) {
            float y = p + b1[h];
            s_y[h] = y / (1.0f + __expf(-y));
        }
    }
    __syncthreads();

    #pragma unroll
    for (int k = 0; k < 4; k++) {
        int m = tid + k*256;
        const float4* wr = (const float4*)(W2 + m*16);
        float4 q0 = __ldg(wr), q1 = __ldg(wr+1), q2 = __ldg(wr+2), q3 = __ldg(wr+3);
        float a;
        a = q0.x*s_y[0];          a = fmaf(q0.y,s_y[1],a);
        a = fmaf(q0.z,s_y[2],a);  a = fmaf(q0.w,s_y[3],a);
        a = fmaf(q1.x,s_y[4],a);  a = fmaf(q1.y,s_y[5],a);
        a = fmaf(q1.z,s_y[6],a);  a = fmaf(q1.w,s_y[7],a);
        a = fmaf(q2.x,s_y[8],a);  a = fmaf(q2.y,s_y[9],a);
        a = fmaf(q2.z,s_y[10],a); a = fmaf(q2.w,s_y[11],a);
        a = fmaf(q3.x,s_y[12],a); a = fmaf(q3.y,s_y[13],a);
        a = fmaf(q3.z,s_y[14],a); a = fmaf(q3.w,s_y[15],a);
        g_lr[i*1024 + m] = a;
    }
}

// ---------------------------------------------------------------------------
// Phase C: second contraction (right-stream). Transposed lr [half][jl][c][20].
// ---------------------------------------------------------------------------
__global__ __launch_bounds__(BLK, 3) void phaseC(const float* __restrict__ x)
{
    __shared__ float s_xi[96], s_xj[48];
    __shared__ __align__(16) float s_RT[2*JCH*16*20];     // 20KB
    __shared__ __align__(16) float s_SMS[JCH*32*20];      // 20KB
    __shared__ __align__(16) float4 s_DF[JCH][32];

    const int tid  = threadIdx.x;
    const int w    = tid >> 5;
    const int lane = tid & 31;
    const int igb  = blockIdx.x >> 5;
    const int js   = blockIdx.x & (JS-1);
    const int i0b  = igb*32;
    const int c    = lane & 15;
    const bool isQ = lane >= 16;

    if (tid < 96)            s_xi[tid]    = x[i0b*3 + tid];
    else if (tid < 144)      s_xj[tid-96] = x[js*JPW*3 + (tid-96)];

    float accP[TI][3];
    #pragma unroll
    for (int t = 0; t < TI; t++)
        #pragma unroll
        for (int b = 0; b < 3; b++) accP[t][b] = 0.f;

    __syncthreads();

    for (int ch = 0; ch < NCH; ch++) {
        const int j0 = js*JPW + ch*JCH;
        if (ch) __syncthreads();
        {   // stage right half of lr transposed
            const float4* src = (const float4*)g_lr;
            #pragma unroll
            for (int k = 0; k < 4; k++) {
                int idx = tid + k*256;          // 0..1023 = 8j * 128
                int jl = idx >> 7, n = idx & 127;
                int half = n >> 6, rem2 = n & 63;
                int r = rem2 >> 2, c4 = (rem2 & 3) << 2;
                float4 v = src[(j0+jl)*256 + 128 + n];
                float* d = &s_RT[((half*JCH + jl)*16 + c4)*20 + r];
                d[0] = v.x; d[20] = v.y; d[40] = v.z; d[60] = v.w;
            }
        }
        gen_pair(s_xi, s_xj, lane, ch*JCH + w, s_SMS, s_DF, w, lane);
        __syncthreads();

        #pragma unroll 4
        for (int jl = 0; jl < JCH; jl++) {
            const float* wp = &s_RT[(isQ ? 2560 : 0) + (jl*16 + c)*20];
            float4 w0 = *(const float4*)(wp);
            float4 w1 = *(const float4*)(wp+4);
            float4 w2 = *(const float4*)(wp+8);
            float4 w3 = *(const float4*)(wp+12);
            const float* smb = &s_SMS[(jl*32 + (w<<2))*20];

            float P[TI];
            #pragma unroll
            for (int t = 0; t < TI; t++) {
                const float* sr = smb + t*20;
                float4 a0 = *(const float4*)(sr);
                float4 a1 = *(const float4*)(sr+4);
                float4 a2 = *(const float4*)(sr+8);
                float4 a3 = *(const float4*)(sr+12);
                float p;
                p = a0.x*w0.x;        p = fmaf(a0.y,w0.y,p);
                p = fmaf(a0.z,w0.z,p); p = fmaf(a0.w,w0.w,p);
                p = fmaf(a1.x,w1.x,p); p = fmaf(a1.y,w1.y,p);
                p = fmaf(a1.z,w1.z,p); p = fmaf(a1.w,w1.w,p);
                p = fmaf(a2.x,w2.x,p); p = fmaf(a2.y,w2.y,p);
                p = fmaf(a2.z,w2.z,p); p = fmaf(a2.w,w2.w,p);
                p = fmaf(a3.x,w3.x,p); p = fmaf(a3.y,w3.y,p);
                p = fmaf(a3.w,w3.w,p); P[t] = fmaf(a3.z,w3.z,p);
            }

            #pragma unroll
            for (int t = 0; t < TI; t++) {
                float4 df = s_DF[jl][(w<<2)+t];
                accP[t][0] = fmaf(P[t], df.x, accP[t][0]);
                accP[t][1] = fmaf(P[t], df.y, accP[t][1]);
                accP[t][2] = fmaf(P[t], df.z, accP[t][2]);
            }
        }
    }

    const int i0 = i0b + w*TI;
    float* outp = isQ ? g_bq2p : g_bk2p;
    #pragma unroll
    for (int t = 0; t < TI; t++)
        #pragma unroll
        for (int b = 0; b < 3; b++)
            outp[(js*NN + (i0+t))*48 + c*3 + b] = accP[t][b];
}

// ---------------------------------------------------------------------------
// Phase D: one i per block (grid 512). Staged merge + left⊗S, att outer,
// MLP2, output.
// ---------------------------------------------------------------------------
__global__ __launch_bounds__(256) void phaseD(const float* __restrict__ W3,
                                              const float* __restrict__ b3,
                                              const float* __restrict__ W4,
                                              const float* __restrict__ b4,
                                              float* __restrict__ out)
{
    const int i = blockIdx.x;
    const int tid = threadIdx.x;
    __shared__ __align__(16) float s_m[2][JS][48];        // 12KB
    __shared__ float s_bk[48], s_bq[48], s_att[256], s_y[16];

    #pragma unroll
    for (int k = 0; k < 3; k++) {
        int idx = tid + k*256;               // 768 = 2*32*12
        if (idx < 2*JS*12) {
            int v = idx / (JS*12), rem = idx % (JS*12);
            int js = rem / 12, f = rem % 12;
            const float4* src = (v == 0) ? (const float4*)g_bk2p
                                         : (const float4*)g_bq2p;
            *(float4*)&s_m[v][js][f*4] = src[(js*NN + i)*12 + f];
        }
    }
    __syncthreads();

    if (tid < 96) {
        int v = tid / 48, e = tid % 48;
        int cc = e / 3, b = e % 3;
        float s = 0.f;
        #pragma unroll
        for (int js = 0; js < JS; js++) s += s_m[v][js][e];
        const float* lp = g_lr + i*1024 + (v ? 256 : 0) + cc;
        const float* sp = g_S  + i*48 + b;
        #pragma unroll
        for (int r = 0; r < 16; r++) s = fmaf(__ldg(&lp[r*16]), __ldg(&sp[r*3]), s);
        if (v == 0) s_bk[e] = s; else s_bq[e] = s;
    }
    __syncthreads();

    {
        int h = tid >> 4, g = tid & 15;
        s_att[tid] = s_bk[h*3+0]*s_bq[g*3+0] + s_bk[h*3+1]*s_bq[g*3+1]
                   + s_bk[h*3+2]*s_bq[g*3+2];
    }
    __syncthreads();

    {
        int h = tid >> 4, t = tid & 15;
        const float* w = W3 + h*256 + t;
        float p = 0.f;
        #pragma unroll
        for (int q = 0; q < 16; q++) p = fmaf(s_att[t + 16*q], __ldg(&w[16*q]), p);
        #pragma unroll
        for (int m = 8; m >= 1; m >>= 1) p += __shfl_xor_sync(0xffffffffu, p, m, 16);
        if (t == 0) {
            float y = p + b3[h];
            s_y[h] = y / (1.0f + __expf(-y));
        }
    }
    __syncthreads();

    if (tid == 0) {
        float a = b4[0];
        #pragma unroll
        for (int o = 0; o < 16; o++) a = fmaf(s_y[o], W4[o], a);
        out[i] = a;
    }
}

// ---------------------------------------------------------------------------
extern "C" void kernel_launch(void* const* d_in, const int* in_sizes, int n_in,
                              void* d_out, int out_size)
{
    const float* x  = (const float*)d_in[0];
    const float* W  = (const float*)d_in[1];
    const float* W1 = (const float*)d_in[2];
    const float* b1 = (const float*)d_in[3];
    const float* W2 = (const float*)d_in[4];
    const float* W3 = (const float*)d_in[5];
    const float* b3 = (const float*)d_in[6];
    const float* W4 = (const float*)d_in[7];
    const float* b4 = (const float*)d_in[8];
    float* out = (float*)d_out;

    phaseA<<<GRID_AC, BLK>>>(x, W);
    phaseB<<<NN, 256>>>(W1, b1, W2);
    phaseC<<<GRID_AC, BLK>>>(x);
    phaseD<<<NN, 256>>>(W3, b3, W4, b4, out);
}